// round 8
// baseline (speedup 1.0000x reference)
#include <cuda_runtime.h>
#include <math.h>

constexpr int Nn = 100000;
constexpr int Ee = 1600000;
constexpr int SCAN_TILE = 1024;
constexpr int NTILES = (Nn + SCAN_TILE - 1) / SCAN_TILE;  // 98

__device__ float d_node[Nn * 64];
__device__ float d_agg[Nn * 64];
__device__ float d_norm[Ee];       // raw edge weight (pre-norm)
__device__ float d_dis[Nn];        // degree -> deg^-0.5 (in place)
__device__ float d_selfnorm[Nn];   // dis[i]^2
__device__ int d_cnt[Nn];
__device__ int d_off[Nn + 1];
__device__ int d_cur[Nn];
__device__ int d_tile[NTILES];
__device__ int d_csr_src[Ee];
__device__ float d_csr_w[Ee];      // fully normalized weight

__device__ __forceinline__ float leaky(float v, float s) {
    return v > 0.0f ? v : s * v;
}

// ---------------------------------------------------------------------------
__global__ void init_kernel() {
    int i = blockIdx.x * blockDim.x + threadIdx.x;
    if (i < Nn) { d_dis[i] = 1.0f; d_cnt[i] = 0; }
}

// ---------------------------------------------------------------------------
// Edge MLP + degree accumulation + CSR count (fused).
__global__ void edge_kernel(const float4* __restrict__ ea,
                            const int* __restrict__ ei,
                            const float* __restrict__ W1,
                            const float* __restrict__ b1,
                            const float* __restrict__ W2,
                            const float* __restrict__ b2) {
    __shared__ float sW1[64];
    __shared__ float sb1[16];
    __shared__ float sW2[16];
    __shared__ float sb2;
    int t = threadIdx.x;
    if (t < 64) sW1[t] = W1[t];
    if (t < 16) sb1[t] = b1[t];
    if (t >= 64 && t < 80) sW2[t - 64] = W2[t - 64];
    if (t == 80) sb2 = b2[0];
    __syncthreads();

    int e = blockIdx.x * blockDim.x + t;
    if (e >= Ee) return;
    float4 a = ea[e];
    float a0 = isnan(a.x) ? 0.0f : a.x;
    float a1 = isnan(a.y) ? 0.0f : a.y;
    float a2 = isnan(a.z) ? 0.0f : a.z;
    float a3 = isnan(a.w) ? 0.0f : a.w;

    float s = sb2;
#pragma unroll
    for (int j = 0; j < 16; j++) {
        float v = a0 * sW1[j] + a1 * sW1[16 + j] + a2 * sW1[32 + j] +
                  a3 * sW1[48 + j] + sb1[j];
        v = leaky(v, 0.2f);
        s += v * sW2[j];
    }
    float ew = leaky(s, 0.005f);
    d_norm[e] = ew;
    int col = ei[Ee + e];
    atomicAdd(&d_dis[col], ew);
    atomicAdd(&d_cnt[col], 1);
}

// ---------------------------------------------------------------------------
__global__ void dis_kernel() {
    int i = blockIdx.x * blockDim.x + threadIdx.x;
    if (i >= Nn) return;
    float d = d_dis[i];
    float r = rsqrtf(d);
    if (isinf(r)) r = 0.0f;
    d_dis[i] = r;
    d_selfnorm[i] = r * r;
}

// ---------------------------------------------------------------------------
// 3-kernel exclusive scan of d_cnt -> d_off, d_cur.
__global__ void scan1_kernel() {
    __shared__ int sh[SCAN_TILE];
    int tid = threadIdx.x;
    int i = blockIdx.x * SCAN_TILE + tid;
    int v = (i < Nn) ? d_cnt[i] : 0;
    sh[tid] = v;
    __syncthreads();
#pragma unroll
    for (int s = 1; s < SCAN_TILE; s <<= 1) {
        int add = (tid >= s) ? sh[tid - s] : 0;
        __syncthreads();
        sh[tid] += add;
        __syncthreads();
    }
    if (i < Nn) d_off[i] = sh[tid];  // inclusive, tile-local (temp)
    if (tid == SCAN_TILE - 1) d_tile[blockIdx.x] = sh[tid];
}

__global__ void scan2_kernel() {
    if (threadIdx.x == 0 && blockIdx.x == 0) {
        int run = 0;
        for (int b = 0; b < NTILES; b++) {
            int s = d_tile[b];
            d_tile[b] = run;
            run += s;
        }
        d_off[Nn] = Ee;
    }
}

__global__ void scan3_kernel() {
    int i = blockIdx.x * blockDim.x + threadIdx.x;
    if (i >= Nn) return;
    int excl = d_off[i] - d_cnt[i] + d_tile[i / SCAN_TILE];
    d_off[i] = excl;
    d_cur[i] = excl;
}

// ---------------------------------------------------------------------------
// CSR fill + norm fusion: csr_w = dis[row] * ew * dis[col].
__global__ void fill_kernel(const int* __restrict__ ei) {
    int e = blockIdx.x * blockDim.x + threadIdx.x;
    if (e >= Ee) return;
    int row = ei[e];
    int col = ei[Ee + e];
    int pos = atomicAdd(&d_cur[col], 1);
    d_csr_src[pos] = row;
    d_csr_w[pos] = d_dis[row] * d_norm[e] * d_dis[col];
}

// ---------------------------------------------------------------------------
// Node MLP stage 1: x[N,7] -> leaky(@Wn1+bn1, 0.2) -> d_agg (as temp)
__global__ void node1_kernel(const float* __restrict__ x,
                             const float* __restrict__ W1,
                             const float* __restrict__ b1) {
    __shared__ float sW[7 * 64];
    __shared__ float sb[64];
    for (int i = threadIdx.x; i < 448; i += blockDim.x) sW[i] = W1[i];
    if (threadIdx.x < 64) sb[threadIdx.x] = b1[threadIdx.x];
    __syncthreads();

    int r = blockIdx.x * blockDim.x + threadIdx.x;
    if (r >= Nn) return;
    float xi[7];
#pragma unroll
    for (int i = 0; i < 7; i++) {
        float v = x[r * 7 + i];
        xi[i] = isnan(v) ? 0.0f : v;
    }
    float4* outp = reinterpret_cast<float4*>(d_agg) + (size_t)r * 16;
#pragma unroll
    for (int j4 = 0; j4 < 16; j4++) {
        float o[4];
#pragma unroll
        for (int c = 0; c < 4; c++) {
            int j = j4 * 4 + c;
            float v = sb[j];
#pragma unroll
            for (int i = 0; i < 7; i++) v += xi[i] * sW[i * 64 + j];
            o[c] = leaky(v, 0.2f);
        }
        outp[j4] = make_float4(o[0], o[1], o[2], o[3]);
    }
}

// ---------------------------------------------------------------------------
// 64x64 GEMM + bias + leaky using packed fma.rn.f32x2 (node MLP / post MLP).
template <bool IN_AGG>
__global__ void __launch_bounds__(256) gemm64_kernel(const float* __restrict__ W,
                                                     const float* __restrict__ b,
                                                     float slope) {
    __shared__ float sW[4096];
    __shared__ float sb[64];
    {
        const float4* W4 = reinterpret_cast<const float4*>(W);
        float4* sW4 = reinterpret_cast<float4*>(sW);
        for (int i = threadIdx.x; i < 1024; i += 256) sW4[i] = W4[i];
        if (threadIdx.x < 64) sb[threadIdx.x] = b[threadIdx.x];
    }
    __syncthreads();

    int r = blockIdx.x * 256 + threadIdx.x;
    if (r >= Nn) return;

    const float* inbase = IN_AGG ? d_agg : d_node;
    const float4* inp = reinterpret_cast<const float4*>(inbase + (size_t)r * 64);

    unsigned long long acc[32];
#pragma unroll
    for (int j = 0; j < 32; j++) {
        asm("mov.b64 %0, {%1, %2};"
            : "=l"(acc[j]) : "f"(sb[2 * j]), "f"(sb[2 * j + 1]));
    }

#pragma unroll 4
    for (int k4 = 0; k4 < 16; k4++) {
        float4 x = inp[k4];
#pragma unroll
        for (int kk = 0; kk < 4; kk++) {
            float xk = (kk == 0) ? x.x : (kk == 1) ? x.y : (kk == 2) ? x.z : x.w;
            unsigned long long xx;
            asm("mov.b64 %0, {%1, %1};" : "=l"(xx) : "f"(xk));
            const ulonglong2* wr = reinterpret_cast<const ulonglong2*>(
                sW + (k4 * 4 + kk) * 64);
#pragma unroll
            for (int j2 = 0; j2 < 16; j2++) {
                ulonglong2 wp = wr[j2];
                asm("fma.rn.f32x2 %0, %1, %2, %0;"
                    : "+l"(acc[2 * j2]) : "l"(xx), "l"(wp.x));
                asm("fma.rn.f32x2 %0, %1, %2, %0;"
                    : "+l"(acc[2 * j2 + 1]) : "l"(xx), "l"(wp.y));
            }
        }
    }

    float* outbase = IN_AGG ? d_node : d_agg;
    float4* outp = reinterpret_cast<float4*>(outbase + (size_t)r * 64);
#pragma unroll
    for (int j4 = 0; j4 < 16; j4++) {
        float o0, o1, o2, o3;
        asm("mov.b64 {%0, %1}, %2;" : "=f"(o0), "=f"(o1) : "l"(acc[2 * j4]));
        asm("mov.b64 {%0, %1}, %2;" : "=f"(o2), "=f"(o3) : "l"(acc[2 * j4 + 1]));
        outp[j4] = make_float4(leaky(o0, slope), leaky(o1, slope),
                               leaky(o2, slope), leaky(o3, slope));
    }
}

// ---------------------------------------------------------------------------
// FUSED GCN layer, block-level: 8 warps x 4 nodes = 32 nodes per block.
// Phase 1 (per warp, round-3 proven gather): acc = selfnorm*in[n] + sum w*in[src]
//         written to padded smem rows.
// Phase 2 (after one __syncthreads): 32x64 @ 64x64 GEMM from smem; thread owns
//         1 row x 8 cols, FFMA2, W broadcast from smem; bias+leaky; store to
//         ping-pong output. GEMM issue overlaps other blocks' gather latency.
constexpr int ROWPAD = 68;  // 64 + 4 floats: kills same-bank row stride
template <bool SWAP>  // false: in=d_node out=d_agg ; true: in=d_agg out=d_node
__global__ void __launch_bounds__(256) layer_kernel(const float* __restrict__ W,
                                                    const float* __restrict__ b) {
    __shared__ float sW[4096];
    __shared__ float sb[64];
    __shared__ float srow[32 * ROWPAD];
    {
        const float4* W4 = reinterpret_cast<const float4*>(W);
        float4* sW4 = reinterpret_cast<float4*>(sW);
        for (int i = threadIdx.x; i < 1024; i += 256) sW4[i] = W4[i];
        if (threadIdx.x < 64) sb[threadIdx.x] = b[threadIdx.x];
    }

    int warp = threadIdx.x >> 5;
    int lane = threadIdx.x & 31;
    const float2* nd = reinterpret_cast<const float2*>(SWAP ? d_agg : d_node);

    int nodebase = blockIdx.x * 32 + warp * 4;
#pragma unroll
    for (int q = 0; q < 4; q++) {
        int n = nodebase + q;
        float sn = d_selfnorm[n];
        float2 self = nd[(size_t)n * 32 + lane];
        float accx = self.x * sn, accy = self.y * sn;

        int i = d_off[n];
        int end = d_off[n + 1];
        for (; i + 4 <= end; i += 4) {
            int s0 = __ldg(&d_csr_src[i + 0]);
            int s1 = __ldg(&d_csr_src[i + 1]);
            int s2 = __ldg(&d_csr_src[i + 2]);
            int s3 = __ldg(&d_csr_src[i + 3]);
            float w0 = __ldg(&d_csr_w[i + 0]);
            float w1 = __ldg(&d_csr_w[i + 1]);
            float w2 = __ldg(&d_csr_w[i + 2]);
            float w3 = __ldg(&d_csr_w[i + 3]);
            float2 v0 = nd[(size_t)s0 * 32 + lane];
            float2 v1 = nd[(size_t)s1 * 32 + lane];
            float2 v2 = nd[(size_t)s2 * 32 + lane];
            float2 v3 = nd[(size_t)s3 * 32 + lane];
            accx += v0.x * w0; accy += v0.y * w0;
            accx += v1.x * w1; accy += v1.y * w1;
            accx += v2.x * w2; accy += v2.y * w2;
            accx += v3.x * w3; accy += v3.y * w3;
        }
        for (; i < end; i++) {
            int s = __ldg(&d_csr_src[i]);
            float w = __ldg(&d_csr_w[i]);
            float2 v = nd[(size_t)s * 32 + lane];
            accx += v.x * w; accy += v.y * w;
        }
        float* row = srow + (warp * 4 + q) * ROWPAD;
        row[2 * lane] = accx;
        row[2 * lane + 1] = accy;
    }
    __syncthreads();

    // GEMM phase: thread -> row r = tid>>3, cols [c0, c0+8)
    int r = threadIdx.x >> 3;
    int c0 = (threadIdx.x & 7) * 8;
    const float* row = srow + r * ROWPAD;

    unsigned long long acc[4];
#pragma unroll
    for (int j = 0; j < 4; j++) {
        asm("mov.b64 %0, {%1, %2};"
            : "=l"(acc[j]) : "f"(sb[c0 + 2 * j]), "f"(sb[c0 + 2 * j + 1]));
    }

#pragma unroll 8
    for (int k = 0; k < 64; k++) {
        float xk = row[k];
        unsigned long long xx;
        asm("mov.b64 %0, {%1, %1};" : "=l"(xx) : "f"(xk));
        const ulonglong2* wp =
            reinterpret_cast<const ulonglong2*>(sW + k * 64 + c0);
        ulonglong2 w01 = wp[0];
        ulonglong2 w23 = wp[1];
        asm("fma.rn.f32x2 %0, %1, %2, %0;" : "+l"(acc[0]) : "l"(xx), "l"(w01.x));
        asm("fma.rn.f32x2 %0, %1, %2, %0;" : "+l"(acc[1]) : "l"(xx), "l"(w01.y));
        asm("fma.rn.f32x2 %0, %1, %2, %0;" : "+l"(acc[2]) : "l"(xx), "l"(w23.x));
        asm("fma.rn.f32x2 %0, %1, %2, %0;" : "+l"(acc[3]) : "l"(xx), "l"(w23.y));
    }

    float o[8];
#pragma unroll
    for (int j = 0; j < 4; j++) {
        asm("mov.b64 {%0, %1}, %2;"
            : "=f"(o[2 * j]), "=f"(o[2 * j + 1]) : "l"(acc[j]));
    }
    int n = blockIdx.x * 32 + r;
    float4* outp = reinterpret_cast<float4*>(SWAP ? d_node : d_agg) +
                   (size_t)n * 16 + (c0 >> 2);
    outp[0] = make_float4(leaky(o[0], 0.2f), leaky(o[1], 0.2f),
                          leaky(o[2], 0.2f), leaky(o[3], 0.2f));
    outp[1] = make_float4(leaky(o[4], 0.2f), leaky(o[5], 0.2f),
                          leaky(o[6], 0.2f), leaky(o[7], 0.2f));
}

// ---------------------------------------------------------------------------
__global__ void final_kernel(const float* __restrict__ Wr,
                             const float* __restrict__ br,
                             float* __restrict__ out) {
    __shared__ float sW[256];
    __shared__ float sb[4];
    if (threadIdx.x < 256) sW[threadIdx.x] = Wr[threadIdx.x];
    if (threadIdx.x < 4) sb[threadIdx.x] = br[threadIdx.x];
    __syncthreads();

    int r = blockIdx.x * blockDim.x + threadIdx.x;
    if (r >= Nn) return;
    const float4* inp = reinterpret_cast<const float4*>(d_node + (size_t)r * 64);
    float acc[4] = {sb[0], sb[1], sb[2], sb[3]};
#pragma unroll
    for (int k4 = 0; k4 < 16; k4++) {
        float4 x = inp[k4];
#pragma unroll
        for (int kk = 0; kk < 4; kk++) {
            float xk = (kk == 0) ? x.x : (kk == 1) ? x.y : (kk == 2) ? x.z : x.w;
            const float* wr = sW + (k4 * 4 + kk) * 4;
            acc[0] += xk * wr[0];
            acc[1] += xk * wr[1];
            acc[2] += xk * wr[2];
            acc[3] += xk * wr[3];
        }
    }
    reinterpret_cast<float4*>(out)[r] = make_float4(acc[0], acc[1], acc[2], acc[3]);
}

// ---------------------------------------------------------------------------
extern "C" void kernel_launch(void* const* d_in, const int* in_sizes, int n_in,
                              void* d_out, int out_size) {
    const float* x = (const float*)d_in[0];
    const int* ei = (const int*)d_in[1];
    const float* ea = (const float*)d_in[2];
    const float* Wn1 = (const float*)d_in[3];
    const float* bn1 = (const float*)d_in[4];
    const float* Wn2 = (const float*)d_in[5];
    const float* bn2 = (const float*)d_in[6];
    const float* We1 = (const float*)d_in[7];
    const float* be1 = (const float*)d_in[8];
    const float* We2 = (const float*)d_in[9];
    const float* be2 = (const float*)d_in[10];
    const float* Wg = (const float*)d_in[11];
    const float* bg = (const float*)d_in[12];
    const float* Wp1 = (const float*)d_in[13];
    const float* bp1 = (const float*)d_in[14];
    const float* Wp2 = (const float*)d_in[15];
    const float* bp2 = (const float*)d_in[16];
    const float* Wr = (const float*)d_in[17];
    const float* br = (const float*)d_in[18];

    const int NB = (Nn + 255) / 256;
    const int EB = (Ee + 255) / 256;
    const int LB = Nn / 32;  // 3125 blocks, 32 nodes each (100000 = 3125*32)

    // gcn_norm + CSR build (norm fused into fill)
    init_kernel<<<NB, 256>>>();
    edge_kernel<<<EB, 256>>>((const float4*)ea, ei, We1, be1, We2, be2);
    dis_kernel<<<NB, 256>>>();
    scan1_kernel<<<NTILES, SCAN_TILE>>>();
    scan2_kernel<<<1, 32>>>();
    scan3_kernel<<<NB, 256>>>();
    fill_kernel<<<EB, 256>>>(ei);

    // node MLP
    node1_kernel<<<NB, 256>>>(x, Wn1, bn1);
    gemm64_kernel<true><<<NB, 256>>>(Wn2, bn2, 0.2f);

    // 8 fused GCN layers, ping-pong d_node <-> d_agg (ends in d_node)
    for (int i = 0; i < 8; i += 2) {
        layer_kernel<false><<<LB, 256>>>(Wg + i * 4096, bg + i * 64);
        layer_kernel<true><<<LB, 256>>>(Wg + (i + 1) * 4096, bg + (i + 1) * 64);
    }

    // post MLP
    gemm64_kernel<false><<<NB, 256>>>(Wp1, bp1, 0.2f);
    gemm64_kernel<true><<<NB, 256>>>(Wp2, bp2, 0.2f);
    final_kernel<<<NB, 256>>>(Wr, br, (float*)d_out);
}

// round 11
// speedup vs baseline: 1.4735x; 1.4735x over previous
#include <cuda_runtime.h>
#include <math.h>

constexpr int Nn = 100000;
constexpr int Ee = 1600000;
constexpr int SCAN_TILE = 1024;
constexpr int NTILES = (Nn + SCAN_TILE - 1) / SCAN_TILE;  // 98

__device__ float d_node[Nn * 64];
__device__ float d_agg[Nn * 64];
__device__ float d_norm[Ee];       // raw edge weight (pre-norm)
__device__ float d_dis[Nn];        // degree -> deg^-0.5 (in place)
__device__ float d_selfnorm[Nn];   // dis[i]^2
__device__ int d_cnt[Nn];
__device__ int d_off[Nn + 1];
__device__ int d_cur[Nn];
__device__ int d_tile[NTILES];
__device__ int2 d_csr[Ee];         // interleaved (src, w_bits) per slot

__device__ __forceinline__ float leaky(float v, float s) {
    return v > 0.0f ? v : s * v;
}

// ---------------------------------------------------------------------------
__global__ void init_kernel() {
    int i = blockIdx.x * blockDim.x + threadIdx.x;
    if (i < Nn) { d_dis[i] = 1.0f; d_cnt[i] = 0; }
}

// ---------------------------------------------------------------------------
// Edge MLP + degree accumulation + CSR count (fused).
__global__ void edge_kernel(const float4* __restrict__ ea,
                            const int* __restrict__ ei,
                            const float* __restrict__ W1,
                            const float* __restrict__ b1,
                            const float* __restrict__ W2,
                            const float* __restrict__ b2) {
    __shared__ float sW1[64];
    __shared__ float sb1[16];
    __shared__ float sW2[16];
    __shared__ float sb2;
    int t = threadIdx.x;
    if (t < 64) sW1[t] = W1[t];
    if (t < 16) sb1[t] = b1[t];
    if (t >= 64 && t < 80) sW2[t - 64] = W2[t - 64];
    if (t == 80) sb2 = b2[0];
    __syncthreads();

    int e = blockIdx.x * blockDim.x + t;
    if (e >= Ee) return;
    float4 a = ea[e];
    float a0 = isnan(a.x) ? 0.0f : a.x;
    float a1 = isnan(a.y) ? 0.0f : a.y;
    float a2 = isnan(a.z) ? 0.0f : a.z;
    float a3 = isnan(a.w) ? 0.0f : a.w;

    float s = sb2;
#pragma unroll
    for (int j = 0; j < 16; j++) {
        float v = a0 * sW1[j] + a1 * sW1[16 + j] + a2 * sW1[32 + j] +
                  a3 * sW1[48 + j] + sb1[j];
        v = leaky(v, 0.2f);
        s += v * sW2[j];
    }
    float ew = leaky(s, 0.005f);
    d_norm[e] = ew;
    int col = ei[Ee + e];
    atomicAdd(&d_dis[col], ew);
    atomicAdd(&d_cnt[col], 1);
}

// ---------------------------------------------------------------------------
__global__ void dis_kernel() {
    int i = blockIdx.x * blockDim.x + threadIdx.x;
    if (i >= Nn) return;
    float d = d_dis[i];
    float r = rsqrtf(d);
    if (isinf(r)) r = 0.0f;
    d_dis[i] = r;
    d_selfnorm[i] = r * r;
}

// ---------------------------------------------------------------------------
// 3-kernel exclusive scan of d_cnt -> d_off, d_cur.
__global__ void scan1_kernel() {
    __shared__ int sh[SCAN_TILE];
    int tid = threadIdx.x;
    int i = blockIdx.x * SCAN_TILE + tid;
    int v = (i < Nn) ? d_cnt[i] : 0;
    sh[tid] = v;
    __syncthreads();
#pragma unroll
    for (int s = 1; s < SCAN_TILE; s <<= 1) {
        int add = (tid >= s) ? sh[tid - s] : 0;
        __syncthreads();
        sh[tid] += add;
        __syncthreads();
    }
    if (i < Nn) d_off[i] = sh[tid];  // inclusive, tile-local (temp)
    if (tid == SCAN_TILE - 1) d_tile[blockIdx.x] = sh[tid];
}

__global__ void scan2_kernel() {
    if (threadIdx.x == 0 && blockIdx.x == 0) {
        int run = 0;
        for (int b = 0; b < NTILES; b++) {
            int s = d_tile[b];
            d_tile[b] = run;
            run += s;
        }
        d_off[Nn] = Ee;
    }
}

__global__ void scan3_kernel() {
    int i = blockIdx.x * blockDim.x + threadIdx.x;
    if (i >= Nn) return;
    int excl = d_off[i] - d_cnt[i] + d_tile[i / SCAN_TILE];
    d_off[i] = excl;
    d_cur[i] = excl;
}

// ---------------------------------------------------------------------------
// CSR fill + norm fusion: slot = (src, bits(dis[row]*ew*dis[col])).
__global__ void fill_kernel(const int* __restrict__ ei) {
    int e = blockIdx.x * blockDim.x + threadIdx.x;
    if (e >= Ee) return;
    int row = ei[e];
    int col = ei[Ee + e];
    int pos = atomicAdd(&d_cur[col], 1);
    float w = d_dis[row] * d_norm[e] * d_dis[col];
    d_csr[pos] = make_int2(row, __float_as_int(w));
}

// ---------------------------------------------------------------------------
// Node MLP stage 1: x[N,7] -> leaky(@Wn1+bn1, 0.2) -> d_agg (as temp)
__global__ void node1_kernel(const float* __restrict__ x,
                             const float* __restrict__ W1,
                             const float* __restrict__ b1) {
    __shared__ float sW[7 * 64];
    __shared__ float sb[64];
    for (int i = threadIdx.x; i < 448; i += blockDim.x) sW[i] = W1[i];
    if (threadIdx.x < 64) sb[threadIdx.x] = b1[threadIdx.x];
    __syncthreads();

    int r = blockIdx.x * blockDim.x + threadIdx.x;
    if (r >= Nn) return;
    float xi[7];
#pragma unroll
    for (int i = 0; i < 7; i++) {
        float v = x[r * 7 + i];
        xi[i] = isnan(v) ? 0.0f : v;
    }
    float4* outp = reinterpret_cast<float4*>(d_agg) + (size_t)r * 16;
#pragma unroll
    for (int j4 = 0; j4 < 16; j4++) {
        float o[4];
#pragma unroll
        for (int c = 0; c < 4; c++) {
            int j = j4 * 4 + c;
            float v = sb[j];
#pragma unroll
            for (int i = 0; i < 7; i++) v += xi[i] * sW[i * 64 + j];
            o[c] = leaky(v, 0.2f);
        }
        outp[j4] = make_float4(o[0], o[1], o[2], o[3]);
    }
}

// ---------------------------------------------------------------------------
// 64x64 GEMM + bias + leaky using packed fma.rn.f32x2 (proven round-3 form).
template <bool IN_AGG>
__global__ void __launch_bounds__(256) gemm64_kernel(const float* __restrict__ W,
                                                     const float* __restrict__ b,
                                                     float slope) {
    __shared__ float sW[4096];
    __shared__ float sb[64];
    {
        const float4* W4 = reinterpret_cast<const float4*>(W);
        float4* sW4 = reinterpret_cast<float4*>(sW);
        for (int i = threadIdx.x; i < 1024; i += 256) sW4[i] = W4[i];
        if (threadIdx.x < 64) sb[threadIdx.x] = b[threadIdx.x];
    }
    __syncthreads();

    int r = blockIdx.x * 256 + threadIdx.x;
    if (r >= Nn) return;

    const float* inbase = IN_AGG ? d_agg : d_node;
    const float4* inp = reinterpret_cast<const float4*>(inbase + (size_t)r * 64);

    unsigned long long acc[32];
#pragma unroll
    for (int j = 0; j < 32; j++) {
        asm("mov.b64 %0, {%1, %2};"
            : "=l"(acc[j]) : "f"(sb[2 * j]), "f"(sb[2 * j + 1]));
    }

#pragma unroll 4
    for (int k4 = 0; k4 < 16; k4++) {
        float4 x = inp[k4];
#pragma unroll
        for (int kk = 0; kk < 4; kk++) {
            float xk = (kk == 0) ? x.x : (kk == 1) ? x.y : (kk == 2) ? x.z : x.w;
            unsigned long long xx;
            asm("mov.b64 %0, {%1, %1};" : "=l"(xx) : "f"(xk));
            const ulonglong2* wr = reinterpret_cast<const ulonglong2*>(
                sW + (k4 * 4 + kk) * 64);
#pragma unroll
            for (int j2 = 0; j2 < 16; j2++) {
                ulonglong2 wp = wr[j2];
                asm("fma.rn.f32x2 %0, %1, %2, %0;"
                    : "+l"(acc[2 * j2]) : "l"(xx), "l"(wp.x));
                asm("fma.rn.f32x2 %0, %1, %2, %0;"
                    : "+l"(acc[2 * j2 + 1]) : "l"(xx), "l"(wp.y));
            }
        }
    }

    float* outbase = IN_AGG ? d_node : d_agg;
    float4* outp = reinterpret_cast<float4*>(outbase + (size_t)r * 64);
#pragma unroll
    for (int j4 = 0; j4 < 16; j4++) {
        float o0, o1, o2, o3;
        asm("mov.b64 {%0, %1}, %2;" : "=f"(o0), "=f"(o1) : "l"(acc[2 * j4]));
        asm("mov.b64 {%0, %1}, %2;" : "=f"(o2), "=f"(o3) : "l"(acc[2 * j4 + 1]));
        outp[j4] = make_float4(leaky(o0, slope), leaky(o1, slope),
                               leaky(o2, slope), leaky(o3, slope));
    }
}

// ---------------------------------------------------------------------------
// Final fused GEMM: agg @ Wp2 + bp2 -> leaky -> (@ Wr + br) -> out[N,4].
// Smem staging is cooperative within the 256-thread block.
__global__ void __launch_bounds__(256) gemm_final_kernel(
    const float* __restrict__ W, const float* __restrict__ b,
    const float* __restrict__ Wr, const float* __restrict__ br,
    float* __restrict__ out) {
    __shared__ float sW[4096];
    __shared__ float sb[64];
    __shared__ float sWr[256];
    __shared__ float sbr[4];
    {
        const float4* W4 = reinterpret_cast<const float4*>(W);
        float4* sW4 = reinterpret_cast<float4*>(sW);
        for (int i = threadIdx.x; i < 1024; i += 256) sW4[i] = W4[i];
        if (threadIdx.x < 64) sb[threadIdx.x] = b[threadIdx.x];
        sWr[threadIdx.x] = Wr[threadIdx.x];   // 256 threads cover all 256
        if (threadIdx.x < 4) sbr[threadIdx.x] = br[threadIdx.x];
    }
    __syncthreads();

    int r = blockIdx.x * 256 + threadIdx.x;
    if (r >= Nn) return;

    const float4* inp = reinterpret_cast<const float4*>(d_agg + (size_t)r * 64);

    unsigned long long acc[32];
#pragma unroll
    for (int j = 0; j < 32; j++) {
        asm("mov.b64 %0, {%1, %2};"
            : "=l"(acc[j]) : "f"(sb[2 * j]), "f"(sb[2 * j + 1]));
    }

#pragma unroll 4
    for (int k4 = 0; k4 < 16; k4++) {
        float4 x = inp[k4];
#pragma unroll
        for (int kk = 0; kk < 4; kk++) {
            float xk = (kk == 0) ? x.x : (kk == 1) ? x.y : (kk == 2) ? x.z : x.w;
            unsigned long long xx;
            asm("mov.b64 %0, {%1, %1};" : "=l"(xx) : "f"(xk));
            const ulonglong2* wr = reinterpret_cast<const ulonglong2*>(
                sW + (k4 * 4 + kk) * 64);
#pragma unroll
            for (int j2 = 0; j2 < 16; j2++) {
                ulonglong2 wp = wr[j2];
                asm("fma.rn.f32x2 %0, %1, %2, %0;"
                    : "+l"(acc[2 * j2]) : "l"(xx), "l"(wp.x));
                asm("fma.rn.f32x2 %0, %1, %2, %0;"
                    : "+l"(acc[2 * j2 + 1]) : "l"(xx), "l"(wp.y));
            }
        }
    }

    // epilogue: o = leaky(acc); out = o @ Wr + br
    float f[4] = {sbr[0], sbr[1], sbr[2], sbr[3]};
#pragma unroll
    for (int j2 = 0; j2 < 32; j2++) {
        float o0, o1;
        asm("mov.b64 {%0, %1}, %2;" : "=f"(o0), "=f"(o1) : "l"(acc[j2]));
        o0 = leaky(o0, 0.2f);
        o1 = leaky(o1, 0.2f);
        const float* w0 = sWr + (2 * j2) * 4;
        const float* w1 = sWr + (2 * j2 + 1) * 4;
        f[0] += o0 * w0[0] + o1 * w1[0];
        f[1] += o0 * w0[1] + o1 * w1[1];
        f[2] += o0 * w0[2] + o1 * w1[2];
        f[3] += o0 * w0[3] + o1 * w1[3];
    }
    reinterpret_cast<float4*>(out)[r] = make_float4(f[0], f[1], f[2], f[3]);
}

// ---------------------------------------------------------------------------
// CSR gather v3: round-3 structure (one warp per node, float2 per lane),
// but csr fetched as interleaved int4 = 2 edges per LDG.128; unroll 8 edges.
__global__ void __launch_bounds__(256) gather_kernel() {
    int warp = (blockIdx.x * blockDim.x + threadIdx.x) >> 5;
    if (warp >= Nn) return;
    int lane = threadIdx.x & 31;

    const float2* nd = reinterpret_cast<const float2*>(d_node);
    float sn = d_selfnorm[warp];
    float2 self = nd[(size_t)warp * 32 + lane];
    float accx = self.x * sn, accy = self.y * sn;

    int i = d_off[warp];
    int end = d_off[warp + 1];
    const int4* cp = reinterpret_cast<const int4*>(d_csr);

    // head peel: make i even (int4 = 2 slots needs 16B alignment)
    if ((i & 1) && i < end) {
        int2 p = d_csr[i];
        float w = __int_as_float(p.y);
        float2 v = nd[(size_t)p.x * 32 + lane];
        accx += v.x * w; accy += v.y * w;
        i++;
    }
    // 8 edges per iteration: 4x LDG.128 uniform + 8 gathered rows in flight
    for (; i + 8 <= end; i += 8) {
        int4 p0 = cp[(i >> 1) + 0];
        int4 p1 = cp[(i >> 1) + 1];
        int4 p2 = cp[(i >> 1) + 2];
        int4 p3 = cp[(i >> 1) + 3];
        float2 v0 = nd[(size_t)p0.x * 32 + lane];
        float2 v1 = nd[(size_t)p0.z * 32 + lane];
        float2 v2 = nd[(size_t)p1.x * 32 + lane];
        float2 v3 = nd[(size_t)p1.z * 32 + lane];
        float2 v4 = nd[(size_t)p2.x * 32 + lane];
        float2 v5 = nd[(size_t)p2.z * 32 + lane];
        float2 v6 = nd[(size_t)p3.x * 32 + lane];
        float2 v7 = nd[(size_t)p3.z * 32 + lane];
        float w0 = __int_as_float(p0.y), w1 = __int_as_float(p0.w);
        float w2 = __int_as_float(p1.y), w3 = __int_as_float(p1.w);
        float w4 = __int_as_float(p2.y), w5 = __int_as_float(p2.w);
        float w6 = __int_as_float(p3.y), w7 = __int_as_float(p3.w);
        accx += v0.x * w0; accy += v0.y * w0;
        accx += v1.x * w1; accy += v1.y * w1;
        accx += v2.x * w2; accy += v2.y * w2;
        accx += v3.x * w3; accy += v3.y * w3;
        accx += v4.x * w4; accy += v4.y * w4;
        accx += v5.x * w5; accy += v5.y * w5;
        accx += v6.x * w6; accy += v6.y * w6;
        accx += v7.x * w7; accy += v7.y * w7;
    }
    // 2 edges per iteration
    for (; i + 2 <= end; i += 2) {
        int4 p = cp[i >> 1];
        float w0 = __int_as_float(p.y), w1 = __int_as_float(p.w);
        float2 v0 = nd[(size_t)p.x * 32 + lane];
        float2 v1 = nd[(size_t)p.z * 32 + lane];
        accx += v0.x * w0; accy += v0.y * w0;
        accx += v1.x * w1; accy += v1.y * w1;
    }
    // tail
    if (i < end) {
        int2 p = d_csr[i];
        float w = __int_as_float(p.y);
        float2 v = nd[(size_t)p.x * 32 + lane];
        accx += v.x * w; accy += v.y * w;
    }
    reinterpret_cast<float2*>(d_agg)[(size_t)warp * 32 + lane] =
        make_float2(accx, accy);
}

// ---------------------------------------------------------------------------
extern "C" void kernel_launch(void* const* d_in, const int* in_sizes, int n_in,
                              void* d_out, int out_size) {
    const float* x = (const float*)d_in[0];
    const int* ei = (const int*)d_in[1];
    const float* ea = (const float*)d_in[2];
    const float* Wn1 = (const float*)d_in[3];
    const float* bn1 = (const float*)d_in[4];
    const float* Wn2 = (const float*)d_in[5];
    const float* bn2 = (const float*)d_in[6];
    const float* We1 = (const float*)d_in[7];
    const float* be1 = (const float*)d_in[8];
    const float* We2 = (const float*)d_in[9];
    const float* be2 = (const float*)d_in[10];
    const float* Wg = (const float*)d_in[11];
    const float* bg = (const float*)d_in[12];
    const float* Wp1 = (const float*)d_in[13];
    const float* bp1 = (const float*)d_in[14];
    const float* Wp2 = (const float*)d_in[15];
    const float* bp2 = (const float*)d_in[16];
    const float* Wr = (const float*)d_in[17];
    const float* br = (const float*)d_in[18];

    const int NB = (Nn + 255) / 256;
    const int EB = (Ee + 255) / 256;
    const int GB = (Nn * 32 + 255) / 256;  // warp per node

    // gcn_norm + CSR build (norm fused into fill, interleaved pairs)
    init_kernel<<<NB, 256>>>();
    edge_kernel<<<EB, 256>>>((const float4*)ea, ei, We1, be1, We2, be2);
    dis_kernel<<<NB, 256>>>();
    scan1_kernel<<<NTILES, SCAN_TILE>>>();
    scan2_kernel<<<1, 32>>>();
    scan3_kernel<<<NB, 256>>>();
    fill_kernel<<<EB, 256>>>(ei);

    // node MLP
    node1_kernel<<<NB, 256>>>(x, Wn1, bn1);
    gemm64_kernel<true><<<NB, 256>>>(Wn2, bn2, 0.2f);

    // 8 GCN layers: interleaved-CSR gather, then GEMM+bias+leaky
    for (int i = 0; i < 8; i++) {
        gather_kernel<<<GB, 256>>>();
        gemm64_kernel<true><<<NB, 256>>>(Wg + i * 4096, bg + i * 64, 0.2f);
    }

    // post MLP: Wp1 gemm, then fused Wp2+final projection
    gemm64_kernel<false><<<NB, 256>>>(Wp1, bp1, 0.2f);
    gemm_final_kernel<<<NB, 256>>>(Wp2, bp2, Wr, br, (float*)d_out);
}

// round 12
// speedup vs baseline: 1.5846x; 1.0754x over previous
#include <cuda_runtime.h>
#include <math.h>

constexpr int Nn = 100000;
constexpr int Ee = 1600000;
constexpr int SCAN_TILE = 1024;
constexpr int NTILES = (Nn + SCAN_TILE - 1) / SCAN_TILE;  // 98

__device__ float d_node[Nn * 64];
__device__ float d_agg[Nn * 64];
__device__ float d_norm[Ee];       // raw edge weight (pre-norm)
__device__ float d_dis[Nn];        // degree -> deg^-0.5 (in place)
__device__ float d_selfnorm[Nn];   // dis[i]^2
__device__ int d_cnt[Nn];
__device__ int d_off[Nn + 1];
__device__ int d_cur[Nn];
__device__ int d_tile[NTILES];
__device__ int d_csr_src[Ee];      // CSR: source node per slot (R3 layout)
__device__ float d_csr_w[Ee];      // CSR: fully normalized weight

__device__ __forceinline__ float leaky(float v, float s) {
    return v > 0.0f ? v : s * v;
}

// ---------------------------------------------------------------------------
__global__ void init_kernel() {
    int i = blockIdx.x * blockDim.x + threadIdx.x;
    if (i < Nn) { d_dis[i] = 1.0f; d_cnt[i] = 0; }
}

// ---------------------------------------------------------------------------
// Edge MLP + degree accumulation + CSR count (fused).
__global__ void edge_kernel(const float4* __restrict__ ea,
                            const int* __restrict__ ei,
                            const float* __restrict__ W1,
                            const float* __restrict__ b1,
                            const float* __restrict__ W2,
                            const float* __restrict__ b2) {
    __shared__ float sW1[64];
    __shared__ float sb1[16];
    __shared__ float sW2[16];
    __shared__ float sb2;
    int t = threadIdx.x;
    if (t < 64) sW1[t] = W1[t];
    if (t < 16) sb1[t] = b1[t];
    if (t >= 64 && t < 80) sW2[t - 64] = W2[t - 64];
    if (t == 80) sb2 = b2[0];
    __syncthreads();

    int e = blockIdx.x * blockDim.x + t;
    if (e >= Ee) return;
    float4 a = ea[e];
    float a0 = isnan(a.x) ? 0.0f : a.x;
    float a1 = isnan(a.y) ? 0.0f : a.y;
    float a2 = isnan(a.z) ? 0.0f : a.z;
    float a3 = isnan(a.w) ? 0.0f : a.w;

    float s = sb2;
#pragma unroll
    for (int j = 0; j < 16; j++) {
        float v = a0 * sW1[j] + a1 * sW1[16 + j] + a2 * sW1[32 + j] +
                  a3 * sW1[48 + j] + sb1[j];
        v = leaky(v, 0.2f);
        s += v * sW2[j];
    }
    float ew = leaky(s, 0.005f);
    d_norm[e] = ew;
    int col = ei[Ee + e];
    atomicAdd(&d_dis[col], ew);
    atomicAdd(&d_cnt[col], 1);
}

// ---------------------------------------------------------------------------
__global__ void dis_kernel() {
    int i = blockIdx.x * blockDim.x + threadIdx.x;
    if (i >= Nn) return;
    float d = d_dis[i];
    float r = rsqrtf(d);
    if (isinf(r)) r = 0.0f;
    d_dis[i] = r;
    d_selfnorm[i] = r * r;
}

// ---------------------------------------------------------------------------
// 3-kernel exclusive scan of d_cnt -> d_off, d_cur.
__global__ void scan1_kernel() {
    __shared__ int sh[SCAN_TILE];
    int tid = threadIdx.x;
    int i = blockIdx.x * SCAN_TILE + tid;
    int v = (i < Nn) ? d_cnt[i] : 0;
    sh[tid] = v;
    __syncthreads();
#pragma unroll
    for (int s = 1; s < SCAN_TILE; s <<= 1) {
        int add = (tid >= s) ? sh[tid - s] : 0;
        __syncthreads();
        sh[tid] += add;
        __syncthreads();
    }
    if (i < Nn) d_off[i] = sh[tid];  // inclusive, tile-local (temp)
    if (tid == SCAN_TILE - 1) d_tile[blockIdx.x] = sh[tid];
}

__global__ void scan2_kernel() {
    if (threadIdx.x == 0 && blockIdx.x == 0) {
        int run = 0;
        for (int b = 0; b < NTILES; b++) {
            int s = d_tile[b];
            d_tile[b] = run;
            run += s;
        }
        d_off[Nn] = Ee;
    }
}

__global__ void scan3_kernel() {
    int i = blockIdx.x * blockDim.x + threadIdx.x;
    if (i >= Nn) return;
    int excl = d_off[i] - d_cnt[i] + d_tile[i / SCAN_TILE];
    d_off[i] = excl;
    d_cur[i] = excl;
}

// ---------------------------------------------------------------------------
// CSR fill + norm fusion: csr_w = dis[row] * ew * dis[col].  (R3 exact)
__global__ void fill_kernel(const int* __restrict__ ei) {
    int e = blockIdx.x * blockDim.x + threadIdx.x;
    if (e >= Ee) return;
    int row = ei[e];
    int col = ei[Ee + e];
    int pos = atomicAdd(&d_cur[col], 1);
    d_csr_src[pos] = row;
    d_csr_w[pos] = d_dis[row] * d_norm[e] * d_dis[col];
}

// ---------------------------------------------------------------------------
// FUSED node MLP: x[N,7] -> leaky(@Wn1+bn1) -> leaky(@Wn2+bn2) -> d_node.
// Row-local chain; second GEMM done in two 32-col halves (register cap).
__global__ void __launch_bounds__(256) node_mlp_kernel(
    const float* __restrict__ x,
    const float* __restrict__ W1, const float* __restrict__ b1,
    const float* __restrict__ W2, const float* __restrict__ b2) {
    __shared__ float sW1[448];
    __shared__ float sb1[64];
    __shared__ float sW2[4096];
    __shared__ float sb2[64];
    {
        for (int i = threadIdx.x; i < 448; i += 256) sW1[i] = W1[i];
        if (threadIdx.x < 64) sb1[threadIdx.x] = b1[threadIdx.x];
        const float4* W4 = reinterpret_cast<const float4*>(W2);
        float4* sW4 = reinterpret_cast<float4*>(sW2);
        for (int i = threadIdx.x; i < 1024; i += 256) sW4[i] = W4[i];
        if (threadIdx.x >= 64 && threadIdx.x < 128)
            sb2[threadIdx.x - 64] = b2[threadIdx.x - 64];
    }
    __syncthreads();

    int r = blockIdx.x * 256 + threadIdx.x;
    if (r >= Nn) return;

    float xi[7];
#pragma unroll
    for (int i = 0; i < 7; i++) {
        float v = x[r * 7 + i];
        xi[i] = isnan(v) ? 0.0f : v;
    }

    // layer 1: h1 = leaky(x @ W1 + b1)
    float h1[64];
#pragma unroll
    for (int j = 0; j < 64; j++) {
        float v = sb1[j];
#pragma unroll
        for (int i = 0; i < 7; i++) v += xi[i] * sW1[i * 64 + j];
        h1[j] = leaky(v, 0.2f);
    }

    // layer 2 in two 32-col halves: h2 = leaky(h1 @ W2 + b2)
    float4* outp = reinterpret_cast<float4*>(d_node) + (size_t)r * 16;
#pragma unroll
    for (int half = 0; half < 2; half++) {
        int c0 = half * 32;
        unsigned long long acc[16];
#pragma unroll
        for (int j = 0; j < 16; j++) {
            asm("mov.b64 %0, {%1, %2};"
                : "=l"(acc[j]) : "f"(sb2[c0 + 2 * j]), "f"(sb2[c0 + 2 * j + 1]));
        }
#pragma unroll
        for (int k = 0; k < 64; k++) {
            unsigned long long xx;
            asm("mov.b64 %0, {%1, %1};" : "=l"(xx) : "f"(h1[k]));
            const ulonglong2* wr =
                reinterpret_cast<const ulonglong2*>(sW2 + k * 64 + c0);
#pragma unroll
            for (int j2 = 0; j2 < 8; j2++) {
                ulonglong2 wp = wr[j2];
                asm("fma.rn.f32x2 %0, %1, %2, %0;"
                    : "+l"(acc[2 * j2]) : "l"(xx), "l"(wp.x));
                asm("fma.rn.f32x2 %0, %1, %2, %0;"
                    : "+l"(acc[2 * j2 + 1]) : "l"(xx), "l"(wp.y));
            }
        }
#pragma unroll
        for (int j4 = 0; j4 < 8; j4++) {
            float o0, o1, o2, o3;
            asm("mov.b64 {%0, %1}, %2;" : "=f"(o0), "=f"(o1) : "l"(acc[2 * j4]));
            asm("mov.b64 {%0, %1}, %2;" : "=f"(o2), "=f"(o3) : "l"(acc[2 * j4 + 1]));
            outp[half * 8 + j4] = make_float4(leaky(o0, 0.2f), leaky(o1, 0.2f),
                                              leaky(o2, 0.2f), leaky(o3, 0.2f));
        }
    }
}

// ---------------------------------------------------------------------------
// 64x64 GEMM + bias + leaky using packed fma.rn.f32x2 (proven round-3 form).
// agg -> node (used by the 8 GCN layers).
__global__ void __launch_bounds__(256) gemm64_kernel(const float* __restrict__ W,
                                                     const float* __restrict__ b,
                                                     float slope) {
    __shared__ float sW[4096];
    __shared__ float sb[64];
    {
        const float4* W4 = reinterpret_cast<const float4*>(W);
        float4* sW4 = reinterpret_cast<float4*>(sW);
        for (int i = threadIdx.x; i < 1024; i += 256) sW4[i] = W4[i];
        if (threadIdx.x < 64) sb[threadIdx.x] = b[threadIdx.x];
    }
    __syncthreads();

    int r = blockIdx.x * 256 + threadIdx.x;
    if (r >= Nn) return;

    const float4* inp = reinterpret_cast<const float4*>(d_agg + (size_t)r * 64);

    unsigned long long acc[32];
#pragma unroll
    for (int j = 0; j < 32; j++) {
        asm("mov.b64 %0, {%1, %2};"
            : "=l"(acc[j]) : "f"(sb[2 * j]), "f"(sb[2 * j + 1]));
    }

#pragma unroll 4
    for (int k4 = 0; k4 < 16; k4++) {
        float4 x = inp[k4];
#pragma unroll
        for (int kk = 0; kk < 4; kk++) {
            float xk = (kk == 0) ? x.x : (kk == 1) ? x.y : (kk == 2) ? x.z : x.w;
            unsigned long long xx;
            asm("mov.b64 %0, {%1, %1};" : "=l"(xx) : "f"(xk));
            const ulonglong2* wr = reinterpret_cast<const ulonglong2*>(
                sW + (k4 * 4 + kk) * 64);
#pragma unroll
            for (int j2 = 0; j2 < 16; j2++) {
                ulonglong2 wp = wr[j2];
                asm("fma.rn.f32x2 %0, %1, %2, %0;"
                    : "+l"(acc[2 * j2]) : "l"(xx), "l"(wp.x));
                asm("fma.rn.f32x2 %0, %1, %2, %0;"
                    : "+l"(acc[2 * j2 + 1]) : "l"(xx), "l"(wp.y));
            }
        }
    }

    float4* outp = reinterpret_cast<float4*>(d_node) + (size_t)r * 16;
#pragma unroll
    for (int j4 = 0; j4 < 16; j4++) {
        float o0, o1, o2, o3;
        asm("mov.b64 {%0, %1}, %2;" : "=f"(o0), "=f"(o1) : "l"(acc[2 * j4]));
        asm("mov.b64 {%0, %1}, %2;" : "=f"(o2), "=f"(o3) : "l"(acc[2 * j4 + 1]));
        outp[j4] = make_float4(leaky(o0, 0.2f), leaky(o1, 0.2f),
                               leaky(o2, 0.2f), leaky(o3, 0.2f));
    }
}

// ---------------------------------------------------------------------------
// FUSED post MLP: d_node -> leaky(@Wp1+bp1) -> leaky(@Wp2+bp2) -> @Wr+br -> out.
// Both 64x64 GEMMs done in two 32-col halves to cap register pressure.
__global__ void __launch_bounds__(256) post_mlp_kernel(
    const float* __restrict__ W1, const float* __restrict__ b1,
    const float* __restrict__ W2, const float* __restrict__ b2,
    const float* __restrict__ Wr, const float* __restrict__ br,
    float* __restrict__ out) {
    __shared__ float sW1[4096];
    __shared__ float sb1[64];
    __shared__ float sW2[4096];
    __shared__ float sb2[64];
    __shared__ float sWr[256];
    __shared__ float sbr[4];
    {
        const float4* W14 = reinterpret_cast<const float4*>(W1);
        const float4* W24 = reinterpret_cast<const float4*>(W2);
        float4* s14 = reinterpret_cast<float4*>(sW1);
        float4* s24 = reinterpret_cast<float4*>(sW2);
        for (int i = threadIdx.x; i < 1024; i += 256) {
            s14[i] = W14[i];
            s24[i] = W24[i];
        }
        if (threadIdx.x < 64) sb1[threadIdx.x] = b1[threadIdx.x];
        if (threadIdx.x >= 64 && threadIdx.x < 128)
            sb2[threadIdx.x - 64] = b2[threadIdx.x - 64];
        sWr[threadIdx.x] = Wr[threadIdx.x];
        if (threadIdx.x < 4) sbr[threadIdx.x] = br[threadIdx.x];
    }
    __syncthreads();

    int r = blockIdx.x * 256 + threadIdx.x;
    if (r >= Nn) return;

    // load input row
    float in[64];
    {
        const float4* inp =
            reinterpret_cast<const float4*>(d_node + (size_t)r * 64);
#pragma unroll
        for (int k4 = 0; k4 < 16; k4++) {
            float4 v = inp[k4];
            in[4 * k4 + 0] = v.x; in[4 * k4 + 1] = v.y;
            in[4 * k4 + 2] = v.z; in[4 * k4 + 3] = v.w;
        }
    }

    // h1 = leaky(in @ W1 + b1), two halves
    float h1[64];
#pragma unroll
    for (int half = 0; half < 2; half++) {
        int c0 = half * 32;
        unsigned long long acc[16];
#pragma unroll
        for (int j = 0; j < 16; j++) {
            asm("mov.b64 %0, {%1, %2};"
                : "=l"(acc[j]) : "f"(sb1[c0 + 2 * j]), "f"(sb1[c0 + 2 * j + 1]));
        }
#pragma unroll
        for (int k = 0; k < 64; k++) {
            unsigned long long xx;
            asm("mov.b64 %0, {%1, %1};" : "=l"(xx) : "f"(in[k]));
            const ulonglong2* wr =
                reinterpret_cast<const ulonglong2*>(sW1 + k * 64 + c0);
#pragma unroll
            for (int j2 = 0; j2 < 8; j2++) {
                ulonglong2 wp = wr[j2];
                asm("fma.rn.f32x2 %0, %1, %2, %0;"
                    : "+l"(acc[2 * j2]) : "l"(xx), "l"(wp.x));
                asm("fma.rn.f32x2 %0, %1, %2, %0;"
                    : "+l"(acc[2 * j2 + 1]) : "l"(xx), "l"(wp.y));
            }
        }
#pragma unroll
        for (int j = 0; j < 16; j++) {
            float o0, o1;
            asm("mov.b64 {%0, %1}, %2;" : "=f"(o0), "=f"(o1) : "l"(acc[j]));
            h1[c0 + 2 * j] = leaky(o0, 0.2f);
            h1[c0 + 2 * j + 1] = leaky(o1, 0.2f);
        }
    }

    // h2 = leaky(h1 @ W2 + b2), fused final projection accumulates into f[4]
    float f[4] = {sbr[0], sbr[1], sbr[2], sbr[3]};
#pragma unroll
    for (int half = 0; half < 2; half++) {
        int c0 = half * 32;
        unsigned long long acc[16];
#pragma unroll
        for (int j = 0; j < 16; j++) {
            asm("mov.b64 %0, {%1, %2};"
                : "=l"(acc[j]) : "f"(sb2[c0 + 2 * j]), "f"(sb2[c0 + 2 * j + 1]));
        }
#pragma unroll
        for (int k = 0; k < 64; k++) {
            unsigned long long xx;
            asm("mov.b64 %0, {%1, %1};" : "=l"(xx) : "f"(h1[k]));
            const ulonglong2* wr =
                reinterpret_cast<const ulonglong2*>(sW2 + k * 64 + c0);
#pragma unroll
            for (int j2 = 0; j2 < 8; j2++) {
                ulonglong2 wp = wr[j2];
                asm("fma.rn.f32x2 %0, %1, %2, %0;"
                    : "+l"(acc[2 * j2]) : "l"(xx), "l"(wp.x));
                asm("fma.rn.f32x2 %0, %1, %2, %0;"
                    : "+l"(acc[2 * j2 + 1]) : "l"(xx), "l"(wp.y));
            }
        }
#pragma unroll
        for (int j = 0; j < 16; j++) {
            float o0, o1;
            asm("mov.b64 {%0, %1}, %2;" : "=f"(o0), "=f"(o1) : "l"(acc[j]));
            o0 = leaky(o0, 0.2f);
            o1 = leaky(o1, 0.2f);
            int col0 = c0 + 2 * j;
            const float* w0 = sWr + col0 * 4;
            const float* w1 = sWr + (col0 + 1) * 4;
            f[0] += o0 * w0[0] + o1 * w1[0];
            f[1] += o0 * w0[1] + o1 * w1[1];
            f[2] += o0 * w0[2] + o1 * w1[2];
            f[3] += o0 * w0[3] + o1 * w1[3];
        }
    }
    reinterpret_cast<float4*>(out)[r] = make_float4(f[0], f[1], f[2], f[3]);
}

// ---------------------------------------------------------------------------
// CSR gather — EXACT round-3 form (measured 871 us config).
__global__ void __launch_bounds__(256) gather_kernel() {
    int warp = (blockIdx.x * blockDim.x + threadIdx.x) >> 5;
    if (warp >= Nn) return;
    int lane = threadIdx.x & 31;

    const float2* nd = reinterpret_cast<const float2*>(d_node);
    float sn = d_selfnorm[warp];
    float2 self = nd[(size_t)warp * 32 + lane];
    float accx = self.x * sn, accy = self.y * sn;

    int i = d_off[warp];
    int end = d_off[warp + 1];

    for (; i + 4 <= end; i += 4) {
        int s0 = __ldg(&d_csr_src[i + 0]);
        int s1 = __ldg(&d_csr_src[i + 1]);
        int s2 = __ldg(&d_csr_src[i + 2]);
        int s3 = __ldg(&d_csr_src[i + 3]);
        float w0 = __ldg(&d_csr_w[i + 0]);
        float w1 = __ldg(&d_csr_w[i + 1]);
        float w2 = __ldg(&d_csr_w[i + 2]);
        float w3 = __ldg(&d_csr_w[i + 3]);
        float2 v0 = nd[(size_t)s0 * 32 + lane];
        float2 v1 = nd[(size_t)s1 * 32 + lane];
        float2 v2 = nd[(size_t)s2 * 32 + lane];
        float2 v3 = nd[(size_t)s3 * 32 + lane];
        accx += v0.x * w0; accy += v0.y * w0;
        accx += v1.x * w1; accy += v1.y * w1;
        accx += v2.x * w2; accy += v2.y * w2;
        accx += v3.x * w3; accy += v3.y * w3;
    }
    for (; i < end; i++) {
        int s = __ldg(&d_csr_src[i]);
        float w = __ldg(&d_csr_w[i]);
        float2 v = nd[(size_t)s * 32 + lane];
        accx += v.x * w; accy += v.y * w;
    }
    reinterpret_cast<float2*>(d_agg)[(size_t)warp * 32 + lane] =
        make_float2(accx, accy);
}

// ---------------------------------------------------------------------------
extern "C" void kernel_launch(void* const* d_in, const int* in_sizes, int n_in,
                              void* d_out, int out_size) {
    const float* x = (const float*)d_in[0];
    const int* ei = (const int*)d_in[1];
    const float* ea = (const float*)d_in[2];
    const float* Wn1 = (const float*)d_in[3];
    const float* bn1 = (const float*)d_in[4];
    const float* Wn2 = (const float*)d_in[5];
    const float* bn2 = (const float*)d_in[6];
    const float* We1 = (const float*)d_in[7];
    const float* be1 = (const float*)d_in[8];
    const float* We2 = (const float*)d_in[9];
    const float* be2 = (const float*)d_in[10];
    const float* Wg = (const float*)d_in[11];
    const float* bg = (const float*)d_in[12];
    const float* Wp1 = (const float*)d_in[13];
    const float* bp1 = (const float*)d_in[14];
    const float* Wp2 = (const float*)d_in[15];
    const float* bp2 = (const float*)d_in[16];
    const float* Wr = (const float*)d_in[17];
    const float* br = (const float*)d_in[18];

    const int NB = (Nn + 255) / 256;
    const int EB = (Ee + 255) / 256;
    const int GB = (Nn * 32 + 255) / 256;  // warp per node

    // gcn_norm + CSR build (norm fused into fill)
    init_kernel<<<NB, 256>>>();
    edge_kernel<<<EB, 256>>>((const float4*)ea, ei, We1, be1, We2, be2);
    dis_kernel<<<NB, 256>>>();
    scan1_kernel<<<NTILES, SCAN_TILE>>>();
    scan2_kernel<<<1, 32>>>();
    scan3_kernel<<<NB, 256>>>();
    fill_kernel<<<EB, 256>>>(ei);

    // fused node MLP: x -> d_node
    node_mlp_kernel<<<NB, 256>>>(x, Wn1, bn1, Wn2, bn2);

    // 8 GCN layers: R3 gather, then GEMM+bias+leaky
    for (int i = 0; i < 8; i++) {
        gather_kernel<<<GB, 256>>>();
        gemm64_kernel<<<NB, 256>>>(Wg + i * 4096, bg + i * 64, 0.2f);
    }

    // fused post MLP + final projection: d_node -> out
    post_mlp_kernel<<<NB, 256>>>(Wp1, bp1, Wp2, bp2, Wr, br, (float*)d_out);
}

// round 13
// speedup vs baseline: 1.6283x; 1.0276x over previous
#include <cuda_runtime.h>
#include <cuda_fp16.h>
#include <math.h>

constexpr int Nn = 100000;
constexpr int Ee = 1600000;
constexpr int SCAN_TILE = 1024;
constexpr int NTILES = (Nn + SCAN_TILE - 1) / SCAN_TILE;  // 98

// d_node: fp16 storage, 32 x half2 (=64 halves, 128B) per row
__device__ unsigned int d_node[Nn * 32];
__device__ float d_agg[Nn * 64];
__device__ float d_norm[Ee];       // raw edge weight (pre-norm)
__device__ float d_dis[Nn];        // degree -> deg^-0.5 (in place)
__device__ float d_selfnorm[Nn];   // dis[i]^2
__device__ int d_cnt[Nn];
__device__ int d_off[Nn + 1];
__device__ int d_cur[Nn];
__device__ int d_tile[NTILES];
__device__ int d_csr_src[Ee];      // CSR: source node per slot (R3 layout)
__device__ float d_csr_w[Ee];      // CSR: fully normalized weight

__device__ __forceinline__ float leaky(float v, float s) {
    return v > 0.0f ? v : s * v;
}

__device__ __forceinline__ unsigned int pack2(float a, float b) {
    __half2 h = __floats2half2_rn(a, b);
    return *reinterpret_cast<unsigned int*>(&h);
}

__device__ __forceinline__ float2 unpack2(unsigned int u) {
    __half2 h = *reinterpret_cast<__half2*>(&u);
    return __half22float2(h);
}

// ---------------------------------------------------------------------------
__global__ void init_kernel() {
    int i = blockIdx.x * blockDim.x + threadIdx.x;
    if (i < Nn) { d_dis[i] = 1.0f; d_cnt[i] = 0; }
}

// ---------------------------------------------------------------------------
// Edge MLP + degree accumulation + CSR count (fused).
__global__ void edge_kernel(const float4* __restrict__ ea,
                            const int* __restrict__ ei,
                            const float* __restrict__ W1,
                            const float* __restrict__ b1,
                            const float* __restrict__ W2,
                            const float* __restrict__ b2) {
    __shared__ float sW1[64];
    __shared__ float sb1[16];
    __shared__ float sW2[16];
    __shared__ float sb2;
    int t = threadIdx.x;
    if (t < 64) sW1[t] = W1[t];
    if (t < 16) sb1[t] = b1[t];
    if (t >= 64 && t < 80) sW2[t - 64] = W2[t - 64];
    if (t == 80) sb2 = b2[0];
    __syncthreads();

    int e = blockIdx.x * blockDim.x + t;
    if (e >= Ee) return;
    float4 a = ea[e];
    float a0 = isnan(a.x) ? 0.0f : a.x;
    float a1 = isnan(a.y) ? 0.0f : a.y;
    float a2 = isnan(a.z) ? 0.0f : a.z;
    float a3 = isnan(a.w) ? 0.0f : a.w;

    float s = sb2;
#pragma unroll
    for (int j = 0; j < 16; j++) {
        float v = a0 * sW1[j] + a1 * sW1[16 + j] + a2 * sW1[32 + j] +
                  a3 * sW1[48 + j] + sb1[j];
        v = leaky(v, 0.2f);
        s += v * sW2[j];
    }
    float ew = leaky(s, 0.005f);
    d_norm[e] = ew;
    int col = ei[Ee + e];
    atomicAdd(&d_dis[col], ew);
    atomicAdd(&d_cnt[col], 1);
}

// ---------------------------------------------------------------------------
__global__ void dis_kernel() {
    int i = blockIdx.x * blockDim.x + threadIdx.x;
    if (i >= Nn) return;
    float d = d_dis[i];
    float r = rsqrtf(d);
    if (isinf(r)) r = 0.0f;
    d_dis[i] = r;
    d_selfnorm[i] = r * r;
}

// ---------------------------------------------------------------------------
// 3-kernel exclusive scan of d_cnt -> d_off, d_cur.
__global__ void scan1_kernel() {
    __shared__ int sh[SCAN_TILE];
    int tid = threadIdx.x;
    int i = blockIdx.x * SCAN_TILE + tid;
    int v = (i < Nn) ? d_cnt[i] : 0;
    sh[tid] = v;
    __syncthreads();
#pragma unroll
    for (int s = 1; s < SCAN_TILE; s <<= 1) {
        int add = (tid >= s) ? sh[tid - s] : 0;
        __syncthreads();
        sh[tid] += add;
        __syncthreads();
    }
    if (i < Nn) d_off[i] = sh[tid];  // inclusive, tile-local (temp)
    if (tid == SCAN_TILE - 1) d_tile[blockIdx.x] = sh[tid];
}

__global__ void scan2_kernel() {
    if (threadIdx.x == 0 && blockIdx.x == 0) {
        int run = 0;
        for (int b = 0; b < NTILES; b++) {
            int s = d_tile[b];
            d_tile[b] = run;
            run += s;
        }
        d_off[Nn] = Ee;
    }
}

__global__ void scan3_kernel() {
    int i = blockIdx.x * blockDim.x + threadIdx.x;
    if (i >= Nn) return;
    int excl = d_off[i] - d_cnt[i] + d_tile[i / SCAN_TILE];
    d_off[i] = excl;
    d_cur[i] = excl;
}

// ---------------------------------------------------------------------------
// CSR fill + norm fusion: csr_w = dis[row] * ew * dis[col].
__global__ void fill_kernel(const int* __restrict__ ei) {
    int e = blockIdx.x * blockDim.x + threadIdx.x;
    if (e >= Ee) return;
    int row = ei[e];
    int col = ei[Ee + e];
    int pos = atomicAdd(&d_cur[col], 1);
    d_csr_src[pos] = row;
    d_csr_w[pos] = d_dis[row] * d_norm[e] * d_dis[col];
}

// ---------------------------------------------------------------------------
// FUSED node MLP: x[N,7] -> leaky(@Wn1+bn1) -> leaky(@Wn2+bn2) -> d_node(fp16).
__global__ void __launch_bounds__(256) node_mlp_kernel(
    const float* __restrict__ x,
    const float* __restrict__ W1, const float* __restrict__ b1,
    const float* __restrict__ W2, const float* __restrict__ b2) {
    __shared__ float sW1[448];
    __shared__ float sb1[64];
    __shared__ float sW2[4096];
    __shared__ float sb2[64];
    {
        for (int i = threadIdx.x; i < 448; i += 256) sW1[i] = W1[i];
        if (threadIdx.x < 64) sb1[threadIdx.x] = b1[threadIdx.x];
        const float4* W4 = reinterpret_cast<const float4*>(W2);
        float4* sW4 = reinterpret_cast<float4*>(sW2);
        for (int i = threadIdx.x; i < 1024; i += 256) sW4[i] = W4[i];
        if (threadIdx.x >= 64 && threadIdx.x < 128)
            sb2[threadIdx.x - 64] = b2[threadIdx.x - 64];
    }
    __syncthreads();

    int r = blockIdx.x * 256 + threadIdx.x;
    if (r >= Nn) return;

    float xi[7];
#pragma unroll
    for (int i = 0; i < 7; i++) {
        float v = x[r * 7 + i];
        xi[i] = isnan(v) ? 0.0f : v;
    }

    float h1[64];
#pragma unroll
    for (int j = 0; j < 64; j++) {
        float v = sb1[j];
#pragma unroll
        for (int i = 0; i < 7; i++) v += xi[i] * sW1[i * 64 + j];
        h1[j] = leaky(v, 0.2f);
    }

    uint4* outp = reinterpret_cast<uint4*>(d_node + (size_t)r * 32);
#pragma unroll
    for (int half = 0; half < 2; half++) {
        int c0 = half * 32;
        unsigned long long acc[16];
#pragma unroll
        for (int j = 0; j < 16; j++) {
            asm("mov.b64 %0, {%1, %2};"
                : "=l"(acc[j]) : "f"(sb2[c0 + 2 * j]), "f"(sb2[c0 + 2 * j + 1]));
        }
#pragma unroll
        for (int k = 0; k < 64; k++) {
            unsigned long long xx;
            asm("mov.b64 %0, {%1, %1};" : "=l"(xx) : "f"(h1[k]));
            const ulonglong2* wr =
                reinterpret_cast<const ulonglong2*>(sW2 + k * 64 + c0);
#pragma unroll
            for (int j2 = 0; j2 < 8; j2++) {
                ulonglong2 wp = wr[j2];
                asm("fma.rn.f32x2 %0, %1, %2, %0;"
                    : "+l"(acc[2 * j2]) : "l"(xx), "l"(wp.x));
                asm("fma.rn.f32x2 %0, %1, %2, %0;"
                    : "+l"(acc[2 * j2 + 1]) : "l"(xx), "l"(wp.y));
            }
        }
        // pack 32 cols -> 4 x uint4 (8 halves each)
#pragma unroll
        for (int q = 0; q < 4; q++) {
            float o[8];
#pragma unroll
            for (int j = 0; j < 4; j++) {
                asm("mov.b64 {%0, %1}, %2;"
                    : "=f"(o[2 * j]), "=f"(o[2 * j + 1]) : "l"(acc[4 * q + j]));
            }
            uint4 pk;
            pk.x = pack2(leaky(o[0], 0.2f), leaky(o[1], 0.2f));
            pk.y = pack2(leaky(o[2], 0.2f), leaky(o[3], 0.2f));
            pk.z = pack2(leaky(o[4], 0.2f), leaky(o[5], 0.2f));
            pk.w = pack2(leaky(o[6], 0.2f), leaky(o[7], 0.2f));
            outp[half * 4 + q] = pk;
        }
    }
}

// ---------------------------------------------------------------------------
// 64x64 GEMM + bias + leaky (FFMA2): d_agg(fp32) -> d_node(fp16).
__global__ void __launch_bounds__(256) gemm64_kernel(const float* __restrict__ W,
                                                     const float* __restrict__ b) {
    __shared__ float sW[4096];
    __shared__ float sb[64];
    {
        const float4* W4 = reinterpret_cast<const float4*>(W);
        float4* sW4 = reinterpret_cast<float4*>(sW);
        for (int i = threadIdx.x; i < 1024; i += 256) sW4[i] = W4[i];
        if (threadIdx.x < 64) sb[threadIdx.x] = b[threadIdx.x];
    }
    __syncthreads();

    int r = blockIdx.x * 256 + threadIdx.x;
    if (r >= Nn) return;

    const float4* inp = reinterpret_cast<const float4*>(d_agg + (size_t)r * 64);

    unsigned long long acc[32];
#pragma unroll
    for (int j = 0; j < 32; j++) {
        asm("mov.b64 %0, {%1, %2};"
            : "=l"(acc[j]) : "f"(sb[2 * j]), "f"(sb[2 * j + 1]));
    }

#pragma unroll 4
    for (int k4 = 0; k4 < 16; k4++) {
        float4 x = inp[k4];
#pragma unroll
        for (int kk = 0; kk < 4; kk++) {
            float xk = (kk == 0) ? x.x : (kk == 1) ? x.y : (kk == 2) ? x.z : x.w;
            unsigned long long xx;
            asm("mov.b64 %0, {%1, %1};" : "=l"(xx) : "f"(xk));
            const ulonglong2* wr = reinterpret_cast<const ulonglong2*>(
                sW + (k4 * 4 + kk) * 64);
#pragma unroll
            for (int j2 = 0; j2 < 16; j2++) {
                ulonglong2 wp = wr[j2];
                asm("fma.rn.f32x2 %0, %1, %2, %0;"
                    : "+l"(acc[2 * j2]) : "l"(xx), "l"(wp.x));
                asm("fma.rn.f32x2 %0, %1, %2, %0;"
                    : "+l"(acc[2 * j2 + 1]) : "l"(xx), "l"(wp.y));
            }
        }
    }

    uint4* outp = reinterpret_cast<uint4*>(d_node + (size_t)r * 32);
#pragma unroll
    for (int q = 0; q < 8; q++) {
        float o[8];
#pragma unroll
        for (int j = 0; j < 4; j++) {
            asm("mov.b64 {%0, %1}, %2;"
                : "=f"(o[2 * j]), "=f"(o[2 * j + 1]) : "l"(acc[4 * q + j]));
        }
        uint4 pk;
        pk.x = pack2(leaky(o[0], 0.2f), leaky(o[1], 0.2f));
        pk.y = pack2(leaky(o[2], 0.2f), leaky(o[3], 0.2f));
        pk.z = pack2(leaky(o[4], 0.2f), leaky(o[5], 0.2f));
        pk.w = pack2(leaky(o[6], 0.2f), leaky(o[7], 0.2f));
        outp[q] = pk;
    }
}

// ---------------------------------------------------------------------------
// FUSED post MLP: d_node(fp16) -> leaky(@Wp1) -> leaky(@Wp2) -> @Wr+br -> out.
__global__ void __launch_bounds__(256) post_mlp_kernel(
    const float* __restrict__ W1, const float* __restrict__ b1,
    const float* __restrict__ W2, const float* __restrict__ b2,
    const float* __restrict__ Wr, const float* __restrict__ br,
    float* __restrict__ out) {
    __shared__ float sW1[4096];
    __shared__ float sb1[64];
    __shared__ float sW2[4096];
    __shared__ float sb2[64];
    __shared__ float sWr[256];
    __shared__ float sbr[4];
    {
        const float4* W14 = reinterpret_cast<const float4*>(W1);
        const float4* W24 = reinterpret_cast<const float4*>(W2);
        float4* s14 = reinterpret_cast<float4*>(sW1);
        float4* s24 = reinterpret_cast<float4*>(sW2);
        for (int i = threadIdx.x; i < 1024; i += 256) {
            s14[i] = W14[i];
            s24[i] = W24[i];
        }
        if (threadIdx.x < 64) sb1[threadIdx.x] = b1[threadIdx.x];
        if (threadIdx.x >= 64 && threadIdx.x < 128)
            sb2[threadIdx.x - 64] = b2[threadIdx.x - 64];
        sWr[threadIdx.x] = Wr[threadIdx.x];
        if (threadIdx.x < 4) sbr[threadIdx.x] = br[threadIdx.x];
    }
    __syncthreads();

    int r = blockIdx.x * 256 + threadIdx.x;
    if (r >= Nn) return;

    // load fp16 input row -> fp32
    float in[64];
    {
        const uint4* inp = reinterpret_cast<const uint4*>(d_node + (size_t)r * 32);
#pragma unroll
        for (int q = 0; q < 8; q++) {
            uint4 pk = inp[q];
            float2 a = unpack2(pk.x), bb = unpack2(pk.y);
            float2 c = unpack2(pk.z), dd = unpack2(pk.w);
            in[8 * q + 0] = a.x; in[8 * q + 1] = a.y;
            in[8 * q + 2] = bb.x; in[8 * q + 3] = bb.y;
            in[8 * q + 4] = c.x; in[8 * q + 5] = c.y;
            in[8 * q + 6] = dd.x; in[8 * q + 7] = dd.y;
        }
    }

    // h1 = leaky(in @ W1 + b1), two halves
    float h1[64];
#pragma unroll
    for (int half = 0; half < 2; half++) {
        int c0 = half * 32;
        unsigned long long acc[16];
#pragma unroll
        for (int j = 0; j < 16; j++) {
            asm("mov.b64 %0, {%1, %2};"
                : "=l"(acc[j]) : "f"(sb1[c0 + 2 * j]), "f"(sb1[c0 + 2 * j + 1]));
        }
#pragma unroll
        for (int k = 0; k < 64; k++) {
            unsigned long long xx;
            asm("mov.b64 %0, {%1, %1};" : "=l"(xx) : "f"(in[k]));
            const ulonglong2* wr =
                reinterpret_cast<const ulonglong2*>(sW1 + k * 64 + c0);
#pragma unroll
            for (int j2 = 0; j2 < 8; j2++) {
                ulonglong2 wp = wr[j2];
                asm("fma.rn.f32x2 %0, %1, %2, %0;"
                    : "+l"(acc[2 * j2]) : "l"(xx), "l"(wp.x));
                asm("fma.rn.f32x2 %0, %1, %2, %0;"
                    : "+l"(acc[2 * j2 + 1]) : "l"(xx), "l"(wp.y));
            }
        }
#pragma unroll
        for (int j = 0; j < 16; j++) {
            float o0, o1;
            asm("mov.b64 {%0, %1}, %2;" : "=f"(o0), "=f"(o1) : "l"(acc[j]));
            h1[c0 + 2 * j] = leaky(o0, 0.2f);
            h1[c0 + 2 * j + 1] = leaky(o1, 0.2f);
        }
    }

    // h2 = leaky(h1 @ W2 + b2) fused with final projection into f[4]
    float f[4] = {sbr[0], sbr[1], sbr[2], sbr[3]};
#pragma unroll
    for (int half = 0; half < 2; half++) {
        int c0 = half * 32;
        unsigned long long acc[16];
#pragma unroll
        for (int j = 0; j < 16; j++) {
            asm("mov.b64 %0, {%1, %2};"
                : "=l"(acc[j]) : "f"(sb2[c0 + 2 * j]), "f"(sb2[c0 + 2 * j + 1]));
        }
#pragma unroll
        for (int k = 0; k < 64; k++) {
            unsigned long long xx;
            asm("mov.b64 %0, {%1, %1};" : "=l"(xx) : "f"(h1[k]));
            const ulonglong2* wr =
                reinterpret_cast<const ulonglong2*>(sW2 + k * 64 + c0);
#pragma unroll
            for (int j2 = 0; j2 < 8; j2++) {
                ulonglong2 wp = wr[j2];
                asm("fma.rn.f32x2 %0, %1, %2, %0;"
                    : "+l"(acc[2 * j2]) : "l"(xx), "l"(wp.x));
                asm("fma.rn.f32x2 %0, %1, %2, %0;"
                    : "+l"(acc[2 * j2 + 1]) : "l"(xx), "l"(wp.y));
            }
        }
#pragma unroll
        for (int j = 0; j < 16; j++) {
            float o0, o1;
            asm("mov.b64 {%0, %1}, %2;" : "=f"(o0), "=f"(o1) : "l"(acc[j]));
            o0 = leaky(o0, 0.2f);
            o1 = leaky(o1, 0.2f);
            int col0 = c0 + 2 * j;
            const float* w0 = sWr + col0 * 4;
            const float* w1 = sWr + (col0 + 1) * 4;
            f[0] += o0 * w0[0] + o1 * w1[0];
            f[1] += o0 * w0[1] + o1 * w1[1];
            f[2] += o0 * w0[2] + o1 * w1[2];
            f[3] += o0 * w0[3] + o1 * w1[3];
        }
    }
    reinterpret_cast<float4*>(out)[r] = make_float4(f[0], f[1], f[2], f[3]);
}

// ---------------------------------------------------------------------------
// CSR gather — R3 structure, fp16 rows: lane loads half2 (warp = 128B row).
__global__ void __launch_bounds__(256) gather_kernel() {
    int warp = (blockIdx.x * blockDim.x + threadIdx.x) >> 5;
    if (warp >= Nn) return;
    int lane = threadIdx.x & 31;

    const __half2* nd = reinterpret_cast<const __half2*>(d_node);
    float sn = d_selfnorm[warp];
    float2 self = __half22float2(nd[(size_t)warp * 32 + lane]);
    float accx = self.x * sn, accy = self.y * sn;

    int i = d_off[warp];
    int end = d_off[warp + 1];

    for (; i + 4 <= end; i += 4) {
        int s0 = __ldg(&d_csr_src[i + 0]);
        int s1 = __ldg(&d_csr_src[i + 1]);
        int s2 = __ldg(&d_csr_src[i + 2]);
        int s3 = __ldg(&d_csr_src[i + 3]);
        float w0 = __ldg(&d_csr_w[i + 0]);
        float w1 = __ldg(&d_csr_w[i + 1]);
        float w2 = __ldg(&d_csr_w[i + 2]);
        float w3 = __ldg(&d_csr_w[i + 3]);
        float2 v0 = __half22float2(nd[(size_t)s0 * 32 + lane]);
        float2 v1 = __half22float2(nd[(size_t)s1 * 32 + lane]);
        float2 v2 = __half22float2(nd[(size_t)s2 * 32 + lane]);
        float2 v3 = __half22float2(nd[(size_t)s3 * 32 + lane]);
        accx += v0.x * w0; accy += v0.y * w0;
        accx += v1.x * w1; accy += v1.y * w1;
        accx += v2.x * w2; accy += v2.y * w2;
        accx += v3.x * w3; accy += v3.y * w3;
    }
    for (; i < end; i++) {
        int s = __ldg(&d_csr_src[i]);
        float w = __ldg(&d_csr_w[i]);
        float2 v = __half22float2(nd[(size_t)s * 32 + lane]);
        accx += v.x * w; accy += v.y * w;
    }
    reinterpret_cast<float2*>(d_agg)[(size_t)warp * 32 + lane] =
        make_float2(accx, accy);
}

// ---------------------------------------------------------------------------
extern "C" void kernel_launch(void* const* d_in, const int* in_sizes, int n_in,
                              void* d_out, int out_size) {
    const float* x = (const float*)d_in[0];
    const int* ei = (const int*)d_in[1];
    const float* ea = (const float*)d_in[2];
    const float* Wn1 = (const float*)d_in[3];
    const float* bn1 = (const float*)d_in[4];
    const float* Wn2 = (const float*)d_in[5];
    const float* bn2 = (const float*)d_in[6];
    const float* We1 = (const float*)d_in[7];
    const float* be1 = (const float*)d_in[8];
    const float* We2 = (const float*)d_in[9];
    const float* be2 = (const float*)d_in[10];
    const float* Wg = (const float*)d_in[11];
    const float* bg = (const float*)d_in[12];
    const float* Wp1 = (const float*)d_in[13];
    const float* bp1 = (const float*)d_in[14];
    const float* Wp2 = (const float*)d_in[15];
    const float* bp2 = (const float*)d_in[16];
    const float* Wr = (const float*)d_in[17];
    const float* br = (const float*)d_in[18];

    const int NB = (Nn + 255) / 256;
    const int EB = (Ee + 255) / 256;
    const int GB = (Nn * 32 + 255) / 256;  // warp per node

    // gcn_norm + CSR build (norm fused into fill)
    init_kernel<<<NB, 256>>>();
    edge_kernel<<<EB, 256>>>((const float4*)ea, ei, We1, be1, We2, be2);
    dis_kernel<<<NB, 256>>>();
    scan1_kernel<<<NTILES, SCAN_TILE>>>();
    scan2_kernel<<<1, 32>>>();
    scan3_kernel<<<NB, 256>>>();
    fill_kernel<<<EB, 256>>>(ei);

    // fused node MLP: x -> d_node (fp16)
    node_mlp_kernel<<<NB, 256>>>(x, Wn1, bn1, Wn2, bn2);

    // 8 GCN layers: fp16 gather, then fp32 GEMM -> fp16 node
    for (int i = 0; i < 8; i++) {
        gather_kernel<<<GB, 256>>>();
        gemm64_kernel<<<NB, 256>>>(Wg + i * 4096, bg + i * 64);
    }

    // fused post MLP + final projection: d_node -> out
    post_mlp_kernel<<<NB, 256>>>(Wp1, bp1, Wp2, bp2, Wr, br, (float*)d_out);
}

// round 14
// speedup vs baseline: 1.9977x; 1.2269x over previous
#include <cuda_runtime.h>
#include <cuda_fp16.h>
#include <math.h>

constexpr int Nn = 100000;
constexpr int Ee = 1600000;
constexpr int SCAN_TILE = 1024;
constexpr int NTILES = (Nn + SCAN_TILE - 1) / SCAN_TILE;  // 98

// fp16 storage: 32 x half2 (=64 halves, 128B) per row
__device__ unsigned int d_node[Nn * 32];
__device__ unsigned int d_agg[Nn * 32];
__device__ float d_norm[Ee];
__device__ float d_dis[Nn];
__device__ float d_selfnorm[Nn];
__device__ int d_cnt[Nn];
__device__ int d_off[Nn + 1];
__device__ int d_cur[Nn];
__device__ int d_tile[NTILES];
__device__ int d_csr_src[Ee];
__device__ float d_csr_w[Ee];

__device__ __forceinline__ float leaky(float v, float s) {
    return v > 0.0f ? v : s * v;
}

__device__ __forceinline__ unsigned int pack2(float a, float b) {
    __half2 h = __floats2half2_rn(a, b);
    return *reinterpret_cast<unsigned int*>(&h);
}

__device__ __forceinline__ float2 unpack2(unsigned int u) {
    __half2 h = *reinterpret_cast<__half2*>(&u);
    return __half22float2(h);
}

// ---------------------------------------------------------------------------
__global__ void init_kernel() {
    int i = blockIdx.x * blockDim.x + threadIdx.x;
    if (i < Nn) { d_dis[i] = 1.0f; d_cnt[i] = 0; }
}

// ---------------------------------------------------------------------------
__global__ void edge_kernel(const float4* __restrict__ ea,
                            const int* __restrict__ ei,
                            const float* __restrict__ W1,
                            const float* __restrict__ b1,
                            const float* __restrict__ W2,
                            const float* __restrict__ b2) {
    __shared__ float sW1[64];
    __shared__ float sb1[16];
    __shared__ float sW2[16];
    __shared__ float sb2;
    int t = threadIdx.x;
    if (t < 64) sW1[t] = W1[t];
    if (t < 16) sb1[t] = b1[t];
    if (t >= 64 && t < 80) sW2[t - 64] = W2[t - 64];
    if (t == 80) sb2 = b2[0];
    __syncthreads();

    int e = blockIdx.x * blockDim.x + t;
    if (e >= Ee) return;
    float4 a = ea[e];
    float a0 = isnan(a.x) ? 0.0f : a.x;
    float a1 = isnan(a.y) ? 0.0f : a.y;
    float a2 = isnan(a.z) ? 0.0f : a.z;
    float a3 = isnan(a.w) ? 0.0f : a.w;

    float s = sb2;
#pragma unroll
    for (int j = 0; j < 16; j++) {
        float v = a0 * sW1[j] + a1 * sW1[16 + j] + a2 * sW1[32 + j] +
                  a3 * sW1[48 + j] + sb1[j];
        v = leaky(v, 0.2f);
        s += v * sW2[j];
    }
    float ew = leaky(s, 0.005f);
    d_norm[e] = ew;
    int col = ei[Ee + e];
    atomicAdd(&d_dis[col], ew);
    atomicAdd(&d_cnt[col], 1);
}

// ---------------------------------------------------------------------------
__global__ void dis_kernel() {
    int i = blockIdx.x * blockDim.x + threadIdx.x;
    if (i >= Nn) return;
    float d = d_dis[i];
    float r = rsqrtf(d);
    if (isinf(r)) r = 0.0f;
    d_dis[i] = r;
    d_selfnorm[i] = r * r;
}

// ---------------------------------------------------------------------------
__global__ void scan1_kernel() {
    __shared__ int sh[SCAN_TILE];
    int tid = threadIdx.x;
    int i = blockIdx.x * SCAN_TILE + tid;
    int v = (i < Nn) ? d_cnt[i] : 0;
    sh[tid] = v;
    __syncthreads();
#pragma unroll
    for (int s = 1; s < SCAN_TILE; s <<= 1) {
        int add = (tid >= s) ? sh[tid - s] : 0;
        __syncthreads();
        sh[tid] += add;
        __syncthreads();
    }
    if (i < Nn) d_off[i] = sh[tid];
    if (tid == SCAN_TILE - 1) d_tile[blockIdx.x] = sh[tid];
}

__global__ void scan2_kernel() {
    if (threadIdx.x == 0 && blockIdx.x == 0) {
        int run = 0;
        for (int b = 0; b < NTILES; b++) {
            int s = d_tile[b];
            d_tile[b] = run;
            run += s;
        }
        d_off[Nn] = Ee;
    }
}

__global__ void scan3_kernel() {
    int i = blockIdx.x * blockDim.x + threadIdx.x;
    if (i >= Nn) return;
    int excl = d_off[i] - d_cnt[i] + d_tile[i / SCAN_TILE];
    d_off[i] = excl;
    d_cur[i] = excl;
}

// ---------------------------------------------------------------------------
__global__ void fill_kernel(const int* __restrict__ ei) {
    int e = blockIdx.x * blockDim.x + threadIdx.x;
    if (e >= Ee) return;
    int row = ei[e];
    int col = ei[Ee + e];
    int pos = atomicAdd(&d_cur[col], 1);
    d_csr_src[pos] = row;
    d_csr_w[pos] = d_dis[row] * d_norm[e] * d_dis[col];
}

// ---------------------------------------------------------------------------
// FUSED node MLP: x[N,7] -> leaky(@Wn1+bn1) -> leaky(@Wn2+bn2) -> d_node(fp16).
__global__ void __launch_bounds__(256) node_mlp_kernel(
    const float* __restrict__ x,
    const float* __restrict__ W1, const float* __restrict__ b1,
    const float* __restrict__ W2, const float* __restrict__ b2) {
    __shared__ float sW1[448];
    __shared__ float sb1[64];
    __shared__ float sW2[4096];
    __shared__ float sb2[64];
    {
        for (int i = threadIdx.x; i < 448; i += 256) sW1[i] = W1[i];
        if (threadIdx.x < 64) sb1[threadIdx.x] = b1[threadIdx.x];
        const float4* W4 = reinterpret_cast<const float4*>(W2);
        float4* sW4 = reinterpret_cast<float4*>(sW2);
        for (int i = threadIdx.x; i < 1024; i += 256) sW4[i] = W4[i];
        if (threadIdx.x >= 64 && threadIdx.x < 128)
            sb2[threadIdx.x - 64] = b2[threadIdx.x - 64];
    }
    __syncthreads();

    int r = blockIdx.x * 256 + threadIdx.x;
    if (r >= Nn) return;

    float xi[7];
#pragma unroll
    for (int i = 0; i < 7; i++) {
        float v = x[r * 7 + i];
        xi[i] = isnan(v) ? 0.0f : v;
    }

    float h1[64];
#pragma unroll
    for (int j = 0; j < 64; j++) {
        float v = sb1[j];
#pragma unroll
        for (int i = 0; i < 7; i++) v += xi[i] * sW1[i * 64 + j];
        h1[j] = leaky(v, 0.2f);
    }

    uint4* outp = reinterpret_cast<uint4*>(d_node + (size_t)r * 32);
#pragma unroll
    for (int half = 0; half < 2; half++) {
        int c0 = half * 32;
        unsigned long long acc[16];
#pragma unroll
        for (int j = 0; j < 16; j++) {
            asm("mov.b64 %0, {%1, %2};"
                : "=l"(acc[j]) : "f"(sb2[c0 + 2 * j]), "f"(sb2[c0 + 2 * j + 1]));
        }
#pragma unroll
        for (int k = 0; k < 64; k++) {
            unsigned long long xx;
            asm("mov.b64 %0, {%1, %1};" : "=l"(xx) : "f"(h1[k]));
            const ulonglong2* wr =
                reinterpret_cast<const ulonglong2*>(sW2 + k * 64 + c0);
#pragma unroll
            for (int j2 = 0; j2 < 8; j2++) {
                ulonglong2 wp = wr[j2];
                asm("fma.rn.f32x2 %0, %1, %2, %0;"
                    : "+l"(acc[2 * j2]) : "l"(xx), "l"(wp.x));
                asm("fma.rn.f32x2 %0, %1, %2, %0;"
                    : "+l"(acc[2 * j2 + 1]) : "l"(xx), "l"(wp.y));
            }
        }
#pragma unroll
        for (int q = 0; q < 4; q++) {
            float o[8];
#pragma unroll
            for (int j = 0; j < 4; j++) {
                asm("mov.b64 {%0, %1}, %2;"
                    : "=f"(o[2 * j]), "=f"(o[2 * j + 1]) : "l"(acc[4 * q + j]));
            }
            uint4 pk;
            pk.x = pack2(leaky(o[0], 0.2f), leaky(o[1], 0.2f));
            pk.y = pack2(leaky(o[2], 0.2f), leaky(o[3], 0.2f));
            pk.z = pack2(leaky(o[4], 0.2f), leaky(o[5], 0.2f));
            pk.w = pack2(leaky(o[6], 0.2f), leaky(o[7], 0.2f));
            outp[half * 4 + q] = pk;
        }
    }
}

// ---------------------------------------------------------------------------
// Tensor-core 64x64 GEMM: d_agg(fp16) @ (W split hi+lo fp16) + b -> leaky
// -> d_node(fp16).  mma.sync.m16n8k16, fp32 accumulate.  Warp = 16 rows.
// W staged transposed [n][k] with 72-half row pad (conflict-free B LDS).
constexpr int WT_STRIDE = 72;
__global__ void __launch_bounds__(256) gemm_tc_kernel(
    const float* __restrict__ W, const float* __restrict__ b) {
    __shared__ __half sWhi[64 * WT_STRIDE];
    __shared__ __half sWlo[64 * WT_STRIDE];
    __shared__ float sb[64];
    for (int i = threadIdx.x; i < 4096; i += 256) {
        int k = i >> 6, n = i & 63;
        float w = W[i];                 // W[k][n] row-major
        __half hi = __float2half_rn(w);
        float lo = w - __half2float(hi);
        sWhi[n * WT_STRIDE + k] = hi;
        sWlo[n * WT_STRIDE + k] = __float2half_rn(lo);
    }
    if (threadIdx.x < 64) sb[threadIdx.x] = b[threadIdx.x];
    __syncthreads();

    int warp = threadIdx.x >> 5;
    int lane = threadIdx.x & 31;
    int tile = blockIdx.x * 8 + warp;
    if (tile >= Nn / 16) return;       // 6250 tiles
    int row0 = tile * 16;
    int qr = lane >> 2;                // 0..7
    int qc = lane & 3;                 // 0..3

    // A fragments for all 4 k-tiles (reused across all n-tiles)
    unsigned int a[4][4];
    {
        const unsigned int* r0p = d_agg + (size_t)(row0 + qr) * 32;
        const unsigned int* r8p = d_agg + (size_t)(row0 + qr + 8) * 32;
#pragma unroll
        for (int kt = 0; kt < 4; kt++) {
            int c = kt * 8 + qc;
            a[kt][0] = r0p[c];
            a[kt][1] = r8p[c];
            a[kt][2] = r0p[c + 4];
            a[kt][3] = r8p[c + 4];
        }
    }

    float acc[8][4];
#pragma unroll
    for (int nt = 0; nt < 8; nt++)
#pragma unroll
        for (int j = 0; j < 4; j++) acc[nt][j] = 0.0f;

#pragma unroll
    for (int kt = 0; kt < 4; kt++) {
#pragma unroll
        for (int nt = 0; nt < 8; nt++) {
            int n = nt * 8 + qr;
            int kh = kt * 16 + qc * 2;  // even -> u32 aligned
            unsigned int bh0 = *reinterpret_cast<const unsigned int*>(
                &sWhi[n * WT_STRIDE + kh]);
            unsigned int bh1 = *reinterpret_cast<const unsigned int*>(
                &sWhi[n * WT_STRIDE + kh + 8]);
            asm volatile(
                "mma.sync.aligned.m16n8k16.row.col.f32.f16.f16.f32 "
                "{%0,%1,%2,%3}, {%4,%5,%6,%7}, {%8,%9}, {%0,%1,%2,%3};"
                : "+f"(acc[nt][0]), "+f"(acc[nt][1]),
                  "+f"(acc[nt][2]), "+f"(acc[nt][3])
                : "r"(a[kt][0]), "r"(a[kt][1]), "r"(a[kt][2]), "r"(a[kt][3]),
                  "r"(bh0), "r"(bh1));
            unsigned int bl0 = *reinterpret_cast<const unsigned int*>(
                &sWlo[n * WT_STRIDE + kh]);
            unsigned int bl1 = *reinterpret_cast<const unsigned int*>(
                &sWlo[n * WT_STRIDE + kh + 8]);
            asm volatile(
                "mma.sync.aligned.m16n8k16.row.col.f32.f16.f16.f32 "
                "{%0,%1,%2,%3}, {%4,%5,%6,%7}, {%8,%9}, {%0,%1,%2,%3};"
                : "+f"(acc[nt][0]), "+f"(acc[nt][1]),
                  "+f"(acc[nt][2]), "+f"(acc[nt][3])
                : "r"(a[kt][0]), "r"(a[kt][1]), "r"(a[kt][2]), "r"(a[kt][3]),
                  "r"(bl0), "r"(bl1));
        }
    }

    // epilogue: bias + leaky + pack fp16 + store
    unsigned int* out0 = d_node + (size_t)(row0 + qr) * 32;
    unsigned int* out8 = d_node + (size_t)(row0 + qr + 8) * 32;
#pragma unroll
    for (int nt = 0; nt < 8; nt++) {
        int col = nt * 8 + qc * 2;
        float b0 = sb[col], b1 = sb[col + 1];
        out0[nt * 4 + qc] = pack2(leaky(acc[nt][0] + b0, 0.2f),
                                  leaky(acc[nt][1] + b1, 0.2f));
        out8[nt * 4 + qc] = pack2(leaky(acc[nt][2] + b0, 0.2f),
                                  leaky(acc[nt][3] + b1, 0.2f));
    }
}

// ---------------------------------------------------------------------------
// FUSED post MLP: d_node(fp16) -> leaky(@Wp1) -> leaky(@Wp2) -> @Wr+br -> out.
__global__ void __launch_bounds__(256) post_mlp_kernel(
    const float* __restrict__ W1, const float* __restrict__ b1,
    const float* __restrict__ W2, const float* __restrict__ b2,
    const float* __restrict__ Wr, const float* __restrict__ br,
    float* __restrict__ out) {
    __shared__ float sW1[4096];
    __shared__ float sb1[64];
    __shared__ float sW2[4096];
    __shared__ float sb2[64];
    __shared__ float sWr[256];
    __shared__ float sbr[4];
    {
        const float4* W14 = reinterpret_cast<const float4*>(W1);
        const float4* W24 = reinterpret_cast<const float4*>(W2);
        float4* s14 = reinterpret_cast<float4*>(sW1);
        float4* s24 = reinterpret_cast<float4*>(sW2);
        for (int i = threadIdx.x; i < 1024; i += 256) {
            s14[i] = W14[i];
            s24[i] = W24[i];
        }
        if (threadIdx.x < 64) sb1[threadIdx.x] = b1[threadIdx.x];
        if (threadIdx.x >= 64 && threadIdx.x < 128)
            sb2[threadIdx.x - 64] = b2[threadIdx.x - 64];
        sWr[threadIdx.x] = Wr[threadIdx.x];
        if (threadIdx.x < 4) sbr[threadIdx.x] = br[threadIdx.x];
    }
    __syncthreads();

    int r = blockIdx.x * 256 + threadIdx.x;
    if (r >= Nn) return;

    float in[64];
    {
        const uint4* inp = reinterpret_cast<const uint4*>(d_node + (size_t)r * 32);
#pragma unroll
        for (int q = 0; q < 8; q++) {
            uint4 pk = inp[q];
            float2 a = unpack2(pk.x), bb = unpack2(pk.y);
            float2 c = unpack2(pk.z), dd = unpack2(pk.w);
            in[8 * q + 0] = a.x; in[8 * q + 1] = a.y;
            in[8 * q + 2] = bb.x; in[8 * q + 3] = bb.y;
            in[8 * q + 4] = c.x; in[8 * q + 5] = c.y;
            in[8 * q + 6] = dd.x; in[8 * q + 7] = dd.y;
        }
    }

    float h1[64];
#pragma unroll
    for (int half = 0; half < 2; half++) {
        int c0 = half * 32;
        unsigned long long acc[16];
#pragma unroll
        for (int j = 0; j < 16; j++) {
            asm("mov.b64 %0, {%1, %2};"
                : "=l"(acc[j]) : "f"(sb1[c0 + 2 * j]), "f"(sb1[c0 + 2 * j + 1]));
        }
#pragma unroll
        for (int k = 0; k < 64; k++) {
            unsigned long long xx;
            asm("mov.b64 %0, {%1, %1};" : "=l"(xx) : "f"(in[k]));
            const ulonglong2* wr =
                reinterpret_cast<const ulonglong2*>(sW1 + k * 64 + c0);
#pragma unroll
            for (int j2 = 0; j2 < 8; j2++) {
                ulonglong2 wp = wr[j2];
                asm("fma.rn.f32x2 %0, %1, %2, %0;"
                    : "+l"(acc[2 * j2]) : "l"(xx), "l"(wp.x));
                asm("fma.rn.f32x2 %0, %1, %2, %0;"
                    : "+l"(acc[2 * j2 + 1]) : "l"(xx), "l"(wp.y));
            }
        }
#pragma unroll
        for (int j = 0; j < 16; j++) {
            float o0, o1;
            asm("mov.b64 {%0, %1}, %2;" : "=f"(o0), "=f"(o1) : "l"(acc[j]));
            h1[c0 + 2 * j] = leaky(o0, 0.2f);
            h1[c0 + 2 * j + 1] = leaky(o1, 0.2f);
        }
    }

    float f[4] = {sbr[0], sbr[1], sbr[2], sbr[3]};
#pragma unroll
    for (int half = 0; half < 2; half++) {
        int c0 = half * 32;
        unsigned long long acc[16];
#pragma unroll
        for (int j = 0; j < 16; j++) {
            asm("mov.b64 %0, {%1, %2};"
                : "=l"(acc[j]) : "f"(sb2[c0 + 2 * j]), "f"(sb2[c0 + 2 * j + 1]));
        }
#pragma unroll
        for (int k = 0; k < 64; k++) {
            unsigned long long xx;
            asm("mov.b64 %0, {%1, %1};" : "=l"(xx) : "f"(h1[k]));
            const ulonglong2* wr =
                reinterpret_cast<const ulonglong2*>(sW2 + k * 64 + c0);
#pragma unroll
            for (int j2 = 0; j2 < 8; j2++) {
                ulonglong2 wp = wr[j2];
                asm("fma.rn.f32x2 %0, %1, %2, %0;"
                    : "+l"(acc[2 * j2]) : "l"(xx), "l"(wp.x));
                asm("fma.rn.f32x2 %0, %1, %2, %0;"
                    : "+l"(acc[2 * j2 + 1]) : "l"(xx), "l"(wp.y));
            }
        }
#pragma unroll
        for (int j = 0; j < 16; j++) {
            float o0, o1;
            asm("mov.b64 {%0, %1}, %2;" : "=f"(o0), "=f"(o1) : "l"(acc[j]));
            o0 = leaky(o0, 0.2f);
            o1 = leaky(o1, 0.2f);
            int col0 = c0 + 2 * j;
            const float* w0 = sWr + col0 * 4;
            const float* w1 = sWr + (col0 + 1) * 4;
            f[0] += o0 * w0[0] + o1 * w1[0];
            f[1] += o0 * w0[1] + o1 * w1[1];
            f[2] += o0 * w0[2] + o1 * w1[2];
            f[3] += o0 * w0[3] + o1 * w1[3];
        }
    }
    reinterpret_cast<float4*>(out)[r] = make_float4(f[0], f[1], f[2], f[3]);
}

// ---------------------------------------------------------------------------
// CSR gather — R3 structure, fp16 rows in AND fp16 agg out.
__global__ void __launch_bounds__(256) gather_kernel() {
    int warp = (blockIdx.x * blockDim.x + threadIdx.x) >> 5;
    if (warp >= Nn) return;
    int lane = threadIdx.x & 31;

    const __half2* nd = reinterpret_cast<const __half2*>(d_node);
    float sn = d_selfnorm[warp];
    float2 self = __half22float2(nd[(size_t)warp * 32 + lane]);
    float accx = self.x * sn, accy = self.y * sn;

    int i = d_off[warp];
    int end = d_off[warp + 1];

    for (; i + 4 <= end; i += 4) {
        int s0 = __ldg(&d_csr_src[i + 0]);
        int s1 = __ldg(&d_csr_src[i + 1]);
        int s2 = __ldg(&d_csr_src[i + 2]);
        int s3 = __ldg(&d_csr_src[i + 3]);
        float w0 = __ldg(&d_csr_w[i + 0]);
        float w1 = __ldg(&d_csr_w[i + 1]);
        float w2 = __ldg(&d_csr_w[i + 2]);
        float w3 = __ldg(&d_csr_w[i + 3]);
        float2 v0 = __half22float2(nd[(size_t)s0 * 32 + lane]);
        float2 v1 = __half22float2(nd[(size_t)s1 * 32 + lane]);
        float2 v2 = __half22float2(nd[(size_t)s2 * 32 + lane]);
        float2 v3 = __half22float2(nd[(size_t)s3 * 32 + lane]);
        accx += v0.x * w0; accy += v0.y * w0;
        accx += v1.x * w1; accy += v1.y * w1;
        accx += v2.x * w2; accy += v2.y * w2;
        accx += v3.x * w3; accy += v3.y * w3;
    }
    for (; i < end; i++) {
        int s = __ldg(&d_csr_src[i]);
        float w = __ldg(&d_csr_w[i]);
        float2 v = __half22float2(nd[(size_t)s * 32 + lane]);
        accx += v.x * w; accy += v.y * w;
    }
    d_agg[(size_t)warp * 32 + lane] = pack2(accx, accy);
}

// ---------------------------------------------------------------------------
extern "C" void kernel_launch(void* const* d_in, const int* in_sizes, int n_in,
                              void* d_out, int out_size) {
    const float* x = (const float*)d_in[0];
    const int* ei = (const int*)d_in[1];
    const float* ea = (const float*)d_in[2];
    const float* Wn1 = (const float*)d_in[3];
    const float* bn1 = (const float*)d_in[4];
    const float* Wn2 = (const float*)d_in[5];
    const float* bn2 = (const float*)d_in[6];
    const float* We1 = (const float*)d_in[7];
    const float* be1 = (const float*)d_in[8];
    const float* We2 = (const float*)d_in[9];
    const float* be2 = (const float*)d_in[10];
    const float* Wg = (const float*)d_in[11];
    const float* bg = (const float*)d_in[12];
    const float* Wp1 = (const float*)d_in[13];
    const float* bp1 = (const float*)d_in[14];
    const float* Wp2 = (const float*)d_in[15];
    const float* bp2 = (const float*)d_in[16];
    const float* Wr = (const float*)d_in[17];
    const float* br = (const float*)d_in[18];

    const int NB = (Nn + 255) / 256;
    const int EB = (Ee + 255) / 256;
    const int GB = (Nn * 32 + 255) / 256;   // gather: warp per node
    const int TB = (Nn / 16 + 7) / 8;       // 782 blocks, warp per 16-row tile

    // gcn_norm + CSR build
    init_kernel<<<NB, 256>>>();
    edge_kernel<<<EB, 256>>>((const float4*)ea, ei, We1, be1, We2, be2);
    dis_kernel<<<NB, 256>>>();
    scan1_kernel<<<NTILES, SCAN_TILE>>>();
    scan2_kernel<<<1, 32>>>();
    scan3_kernel<<<NB, 256>>>();
    fill_kernel<<<EB, 256>>>(ei);

    // fused node MLP: x -> d_node (fp16)
    node_mlp_kernel<<<NB, 256>>>(x, Wn1, bn1, Wn2, bn2);

    // 8 GCN layers: fp16 gather -> tensor-core GEMM (split-W) -> fp16 node
    for (int i = 0; i < 8; i++) {
        gather_kernel<<<GB, 256>>>();
        gemm_tc_kernel<<<TB, 256>>>(Wg + i * 4096, bg + i * 64);
    }

    // fused post MLP + final projection
    post_mlp_kernel<<<NB, 256>>>(Wp1, bp1, Wp2, bp2, Wr, br, (float*)d_out);
}

// round 17
// speedup vs baseline: 2.2366x; 1.1196x over previous
#include <cuda_runtime.h>
#include <cuda_fp16.h>
#include <math.h>

constexpr int Nn = 100000;
constexpr int Ee = 1600000;
constexpr int SCAN_TILE = 1024;
constexpr int NTILES = (Nn + SCAN_TILE - 1) / SCAN_TILE;  // 98

// fp16 storage: 32 x half2 (=64 halves, 128B) per row
__device__ unsigned int d_node[Nn * 32];
__device__ unsigned int d_agg[Nn * 32];
__device__ float d_norm[Ee];
__device__ float d_dis[Nn];
__device__ float d_selfnorm[Nn];
__device__ int d_cnt[Nn];
__device__ int d_off[Nn + 1];
__device__ int d_cur[Nn];
__device__ int d_tile[NTILES];
__device__ int d_csr_src[Ee];
__device__ float d_csr_w[Ee];
// split-fp16 GCN weights, transposed [layer][n][k], dense 64x64
__device__ __half d_wg_hi[8 * 4096];
__device__ __half d_wg_lo[8 * 4096];

__device__ __forceinline__ float leaky(float v, float s) {
    return v > 0.0f ? v : s * v;
}

__device__ __forceinline__ unsigned int pack2(float a, float b) {
    __half2 h = __floats2half2_rn(a, b);
    return *reinterpret_cast<unsigned int*>(&h);
}

__device__ __forceinline__ float2 unpack2(unsigned int u) {
    __half2 h = *reinterpret_cast<__half2*>(&u);
    return __half22float2(h);
}

// ---------------------------------------------------------------------------
__global__ void init_kernel() {
    int i = blockIdx.x * blockDim.x + threadIdx.x;
    if (i < Nn) { d_dis[i] = 1.0f; d_cnt[i] = 0; }
}

// ---------------------------------------------------------------------------
// One-time split of Wg into hi/lo fp16, transposed [n][k].
__global__ void wsplit_kernel(const float* __restrict__ Wg) {
    int i = blockIdx.x * blockDim.x + threadIdx.x;
    if (i >= 8 * 4096) return;
    int l = i >> 12;
    int k = (i >> 6) & 63;
    int n = i & 63;
    float w = Wg[i];  // Wg[l][k][n]
    __half hi = __float2half_rn(w);
    float lo = w - __half2float(hi);
    d_wg_hi[l * 4096 + n * 64 + k] = hi;
    d_wg_lo[l * 4096 + n * 64 + k] = __float2half_rn(lo);
}

// ---------------------------------------------------------------------------
__global__ void edge_kernel(const float4* __restrict__ ea,
                            const int* __restrict__ ei,
                            const float* __restrict__ W1,
                            const float* __restrict__ b1,
                            const float* __restrict__ W2,
                            const float* __restrict__ b2) {
    __shared__ float sW1[64];
    __shared__ float sb1[16];
    __shared__ float sW2[16];
    __shared__ float sb2;
    int t = threadIdx.x;
    if (t < 64) sW1[t] = W1[t];
    if (t < 16) sb1[t] = b1[t];
    if (t >= 64 && t < 80) sW2[t - 64] = W2[t - 64];
    if (t == 80) sb2 = b2[0];
    __syncthreads();

    int e = blockIdx.x * blockDim.x + t;
    if (e >= Ee) return;
    float4 a = ea[e];
    float a0 = isnan(a.x) ? 0.0f : a.x;
    float a1 = isnan(a.y) ? 0.0f : a.y;
    float a2 = isnan(a.z) ? 0.0f : a.z;
    float a3 = isnan(a.w) ? 0.0f : a.w;

    float s = sb2;
#pragma unroll
    for (int j = 0; j < 16; j++) {
        float v = a0 * sW1[j] + a1 * sW1[16 + j] + a2 * sW1[32 + j] +
                  a3 * sW1[48 + j] + sb1[j];
        v = leaky(v, 0.2f);
        s += v * sW2[j];
    }
    float ew = leaky(s, 0.005f);
    d_norm[e] = ew;
    int col = ei[Ee + e];
    atomicAdd(&d_dis[col], ew);
    atomicAdd(&d_cnt[col], 1);
}

// ---------------------------------------------------------------------------
__global__ void scan1_kernel() {
    __shared__ int sh[SCAN_TILE];
    int tid = threadIdx.x;
    int i = blockIdx.x * SCAN_TILE + tid;
    int v = (i < Nn) ? d_cnt[i] : 0;
    sh[tid] = v;
    __syncthreads();
#pragma unroll
    for (int s = 1; s < SCAN_TILE; s <<= 1) {
        int add = (tid >= s) ? sh[tid - s] : 0;
        __syncthreads();
        sh[tid] += add;
        __syncthreads();
    }
    if (i < Nn) d_off[i] = sh[tid];
    if (tid == SCAN_TILE - 1) d_tile[blockIdx.x] = sh[tid];
}

__global__ void scan2_kernel() {
    if (threadIdx.x == 0 && blockIdx.x == 0) {
        int run = 0;
        for (int b = 0; b < NTILES; b++) {
            int s = d_tile[b];
            d_tile[b] = run;
            run += s;
        }
        d_off[Nn] = Ee;
    }
}

// scan3 + dis fused: finalize offsets/cursors AND deg^-0.5 / selfnorm.
__global__ void scan3_kernel() {
    int i = blockIdx.x * blockDim.x + threadIdx.x;
    if (i >= Nn) return;
    int excl = d_off[i] - d_cnt[i] + d_tile[i / SCAN_TILE];
    d_off[i] = excl;
    d_cur[i] = excl;
    float d = d_dis[i];
    float r = rsqrtf(d);
    if (isinf(r)) r = 0.0f;
    d_dis[i] = r;
    d_selfnorm[i] = r * r;
}

// ---------------------------------------------------------------------------
__global__ void fill_kernel(const int* __restrict__ ei) {
    int e = blockIdx.x * blockDim.x + threadIdx.x;
    if (e >= Ee) return;
    int row = ei[e];
    int col = ei[Ee + e];
    int pos = atomicAdd(&d_cur[col], 1);
    d_csr_src[pos] = row;
    d_csr_w[pos] = d_dis[row] * d_norm[e] * d_dis[col];
}

// ---------------------------------------------------------------------------
// FUSED node MLP: x[N,7] -> leaky(@Wn1+bn1) -> leaky(@Wn2+bn2) -> d_node(fp16).
__global__ void __launch_bounds__(256) node_mlp_kernel(
    const float* __restrict__ x,
    const float* __restrict__ W1, const float* __restrict__ b1,
    const float* __restrict__ W2, const float* __restrict__ b2) {
    __shared__ float sW1[448];
    __shared__ float sb1[64];
    __shared__ float sW2[4096];
    __shared__ float sb2[64];
    {
        for (int i = threadIdx.x; i < 448; i += 256) sW1[i] = W1[i];
        if (threadIdx.x < 64) sb1[threadIdx.x] = b1[threadIdx.x];
        const float4* W4 = reinterpret_cast<const float4*>(W2);
        float4* sW4 = reinterpret_cast<float4*>(sW2);
        for (int i = threadIdx.x; i < 1024; i += 256) sW4[i] = W4[i];
        if (threadIdx.x >= 64 && threadIdx.x < 128)
            sb2[threadIdx.x - 64] = b2[threadIdx.x - 64];
    }
    __syncthreads();

    int r = blockIdx.x * 256 + threadIdx.x;
    if (r >= Nn) return;

    float xi[7];
#pragma unroll
    for (int i = 0; i < 7; i++) {
        float v = x[r * 7 + i];
        xi[i] = isnan(v) ? 0.0f : v;
    }

    float h1[64];
#pragma unroll
    for (int j = 0; j < 64; j++) {
        float v = sb1[j];
#pragma unroll
        for (int i = 0; i < 7; i++) v += xi[i] * sW1[i * 64 + j];
        h1[j] = leaky(v, 0.2f);
    }

    uint4* outp = reinterpret_cast<uint4*>(d_node + (size_t)r * 32);
#pragma unroll
    for (int half = 0; half < 2; half++) {
        int c0 = half * 32;
        unsigned long long acc[16];
#pragma unroll
        for (int j = 0; j < 16; j++) {
            asm("mov.b64 %0, {%1, %2};"
                : "=l"(acc[j]) : "f"(sb2[c0 + 2 * j]), "f"(sb2[c0 + 2 * j + 1]));
        }
#pragma unroll
        for (int k = 0; k < 64; k++) {
            unsigned long long xx;
            asm("mov.b64 %0, {%1, %1};" : "=l"(xx) : "f"(h1[k]));
            const ulonglong2* wr =
                reinterpret_cast<const ulonglong2*>(sW2 + k * 64 + c0);
#pragma unroll
            for (int j2 = 0; j2 < 8; j2++) {
                ulonglong2 wp = wr[j2];
                asm("fma.rn.f32x2 %0, %1, %2, %0;"
                    : "+l"(acc[2 * j2]) : "l"(xx), "l"(wp.x));
                asm("fma.rn.f32x2 %0, %1, %2, %0;"
                    : "+l"(acc[2 * j2 + 1]) : "l"(xx), "l"(wp.y));
            }
        }
#pragma unroll
        for (int q = 0; q < 4; q++) {
            float o[8];
#pragma unroll
            for (int j = 0; j < 4; j++) {
                asm("mov.b64 {%0, %1}, %2;"
                    : "=f"(o[2 * j]), "=f"(o[2 * j + 1]) : "l"(acc[4 * q + j]));
            }
            uint4 pk;
            pk.x = pack2(leaky(o[0], 0.2f), leaky(o[1], 0.2f));
            pk.y = pack2(leaky(o[2], 0.2f), leaky(o[3], 0.2f));
            pk.z = pack2(leaky(o[4], 0.2f), leaky(o[5], 0.2f));
            pk.w = pack2(leaky(o[6], 0.2f), leaky(o[7], 0.2f));
            outp[half * 4 + q] = pk;
        }
    }
}

// ---------------------------------------------------------------------------
// Tensor-core 64x64 GEMM: d_agg(fp16) @ (precomputed split W) + b -> leaky
// -> d_node(fp16).  mma.sync.m16n8k16 fp32 acc.  Warp = 16 rows.
// Layer index passed as int; W resolved from __device__ symbols in device code.
constexpr int WT_STRIDE = 72;
__global__ void __launch_bounds__(256) gemm_tc_kernel(
    int layer, const float* __restrict__ b) {
    __shared__ __half sWhi[64 * WT_STRIDE];
    __shared__ __half sWlo[64 * WT_STRIDE];
    __shared__ float sb[64];
    {
        const uint4* src_hi =
            reinterpret_cast<const uint4*>(d_wg_hi + layer * 4096);
        const uint4* src_lo =
            reinterpret_cast<const uint4*>(d_wg_lo + layer * 4096);
        for (int i = threadIdx.x; i < 512; i += 256) {
            int n = i >> 3, kq = i & 7;
            *reinterpret_cast<uint4*>(&sWhi[n * WT_STRIDE + kq * 8]) = src_hi[i];
            *reinterpret_cast<uint4*>(&sWlo[n * WT_STRIDE + kq * 8]) = src_lo[i];
        }
        if (threadIdx.x < 64) sb[threadIdx.x] = b[threadIdx.x];
    }
    __syncthreads();

    int warp = threadIdx.x >> 5;
    int lane = threadIdx.x & 31;
    int tile = blockIdx.x * 8 + warp;
    if (tile >= Nn / 16) return;  // 6250 tiles
    int row0 = tile * 16;
    int qr = lane >> 2;
    int qc = lane & 3;

    unsigned int a[4][4];
    {
        const unsigned int* r0p = d_agg + (size_t)(row0 + qr) * 32;
        const unsigned int* r8p = d_agg + (size_t)(row0 + qr + 8) * 32;
#pragma unroll
        for (int kt = 0; kt < 4; kt++) {
            int c = kt * 8 + qc;
            a[kt][0] = r0p[c];
            a[kt][1] = r8p[c];
            a[kt][2] = r0p[c + 4];
            a[kt][3] = r8p[c + 4];
        }
    }

    float acc[8][4];
#pragma unroll
    for (int nt = 0; nt < 8; nt++)
#pragma unroll
        for (int j = 0; j < 4; j++) acc[nt][j] = 0.0f;

#pragma unroll
    for (int kt = 0; kt < 4; kt++) {
#pragma unroll
        for (int nt = 0; nt < 8; nt++) {
            int n = nt * 8 + qr;
            int kh = kt * 16 + qc * 2;
            unsigned int bh0 = *reinterpret_cast<const unsigned int*>(
                &sWhi[n * WT_STRIDE + kh]);
            unsigned int bh1 = *reinterpret_cast<const unsigned int*>(
                &sWhi[n * WT_STRIDE + kh + 8]);
            asm volatile(
                "mma.sync.aligned.m16n8k16.row.col.f32.f16.f16.f32 "
                "{%0,%1,%2,%3}, {%4,%5,%6,%7}, {%8,%9}, {%0,%1,%2,%3};"
                : "+f"(acc[nt][0]), "+f"(acc[nt][1]),
                  "+f"(acc[nt][2]), "+f"(acc[nt][3])
                : "r"(a[kt][0]), "r"(a[kt][1]), "r"(a[kt][2]), "r"(a[kt][3]),
                  "r"(bh0), "r"(bh1));
            unsigned int bl0 = *reinterpret_cast<const unsigned int*>(
                &sWlo[n * WT_STRIDE + kh]);
            unsigned int bl1 = *reinterpret_cast<const unsigned int*>(
                &sWlo[n * WT_STRIDE + kh + 8]);
            asm volatile(
                "mma.sync.aligned.m16n8k16.row.col.f32.f16.f16.f32 "
                "{%0,%1,%2,%3}, {%4,%5,%6,%7}, {%8,%9}, {%0,%1,%2,%3};"
                : "+f"(acc[nt][0]), "+f"(acc[nt][1]),
                  "+f"(acc[nt][2]), "+f"(acc[nt][3])
                : "r"(a[kt][0]), "r"(a[kt][1]), "r"(a[kt][2]), "r"(a[kt][3]),
                  "r"(bl0), "r"(bl1));
        }
    }

    unsigned int* out0 = d_node + (size_t)(row0 + qr) * 32;
    unsigned int* out8 = d_node + (size_t)(row0 + qr + 8) * 32;
#pragma unroll
    for (int nt = 0; nt < 8; nt++) {
        int col = nt * 8 + qc * 2;
        float b0 = sb[col], b1 = sb[col + 1];
        out0[nt * 4 + qc] = pack2(leaky(acc[nt][0] + b0, 0.2f),
                                  leaky(acc[nt][1] + b1, 0.2f));
        out8[nt * 4 + qc] = pack2(leaky(acc[nt][2] + b0, 0.2f),
                                  leaky(acc[nt][3] + b1, 0.2f));
    }
}

// ---------------------------------------------------------------------------
// FUSED post MLP: d_node(fp16) -> leaky(@Wp1) -> leaky(@Wp2) -> @Wr+br -> out.
__global__ void __launch_bounds__(256) post_mlp_kernel(
    const float* __restrict__ W1, const float* __restrict__ b1,
    const float* __restrict__ W2, const float* __restrict__ b2,
    const float* __restrict__ Wr, const float* __restrict__ br,
    float* __restrict__ out) {
    __shared__ float sW1[4096];
    __shared__ float sb1[64];
    __shared__ float sW2[4096];
    __shared__ float sb2[64];
    __shared__ float sWr[256];
    __shared__ float sbr[4];
    {
        const float4* W14 = reinterpret_cast<const float4*>(W1);
        const float4* W24 = reinterpret_cast<const float4*>(W2);
        float4* s14 = reinterpret_cast<float4*>(sW1);
        float4* s24 = reinterpret_cast<float4*>(sW2);
        for (int i = threadIdx.x; i < 1024; i += 256) {
            s14[i] = W14[i];
            s24[i] = W24[i];
        }
        if (threadIdx.x < 64) sb1[threadIdx.x] = b1[threadIdx.x];
        if (threadIdx.x >= 64 && threadIdx.x < 128)
            sb2[threadIdx.x - 64] = b2[threadIdx.x - 64];
        sWr[threadIdx.x] = Wr[threadIdx.x];
        if (threadIdx.x < 4) sbr[threadIdx.x] = br[threadIdx.x];
    }
    __syncthreads();

    int r = blockIdx.x * 256 + threadIdx.x;
    if (r >= Nn) return;

    float in[64];
    {
        const uint4* inp = reinterpret_cast<const uint4*>(d_node + (size_t)r * 32);
#pragma unroll
        for (int q = 0; q < 8; q++) {
            uint4 pk = inp[q];
            float2 a = unpack2(pk.x), bb = unpack2(pk.y);
            float2 c = unpack2(pk.z), dd = unpack2(pk.w);
            in[8 * q + 0] = a.x; in[8 * q + 1] = a.y;
            in[8 * q + 2] = bb.x; in[8 * q + 3] = bb.y;
            in[8 * q + 4] = c.x; in[8 * q + 5] = c.y;
            in[8 * q + 6] = dd.x; in[8 * q + 7] = dd.y;
        }
    }

    float h1[64];
#pragma unroll
    for (int half = 0; half < 2; half++) {
        int c0 = half * 32;
        unsigned long long acc[16];
#pragma unroll
        for (int j = 0; j < 16; j++) {
            asm("mov.b64 %0, {%1, %2};"
                : "=l"(acc[j]) : "f"(sb1[c0 + 2 * j]), "f"(sb1[c0 + 2 * j + 1]));
        }
#pragma unroll
        for (int k = 0; k < 64; k++) {
            unsigned long long xx;
            asm("mov.b64 %0, {%1, %1};" : "=l"(xx) : "f"(in[k]));
            const ulonglong2* wr =
                reinterpret_cast<const ulonglong2*>(sW1 + k * 64 + c0);
#pragma unroll
            for (int j2 = 0; j2 < 8; j2++) {
                ulonglong2 wp = wr[j2];
                asm("fma.rn.f32x2 %0, %1, %2, %0;"
                    : "+l"(acc[2 * j2]) : "l"(xx), "l"(wp.x));
                asm("fma.rn.f32x2 %0, %1, %2, %0;"
                    : "+l"(acc[2 * j2 + 1]) : "l"(xx), "l"(wp.y));
            }
        }
#pragma unroll
        for (int j = 0; j < 16; j++) {
            float o0, o1;
            asm("mov.b64 {%0, %1}, %2;" : "=f"(o0), "=f"(o1) : "l"(acc[j]));
            h1[c0 + 2 * j] = leaky(o0, 0.2f);
            h1[c0 + 2 * j + 1] = leaky(o1, 0.2f);
        }
    }

    float f[4] = {sbr[0], sbr[1], sbr[2], sbr[3]};
#pragma unroll
    for (int half = 0; half < 2; half++) {
        int c0 = half * 32;
        unsigned long long acc[16];
#pragma unroll
        for (int j = 0; j < 16; j++) {
            asm("mov.b64 %0, {%1, %2};"
                : "=l"(acc[j]) : "f"(sb2[c0 + 2 * j]), "f"(sb2[c0 + 2 * j + 1]));
        }
#pragma unroll
        for (int k = 0; k < 64; k++) {
            unsigned long long xx;
            asm("mov.b64 %0, {%1, %1};" : "=l"(xx) : "f"(h1[k]));
            const ulonglong2* wr =
                reinterpret_cast<const ulonglong2*>(sW2 + k * 64 + c0);
#pragma unroll
            for (int j2 = 0; j2 < 8; j2++) {
                ulonglong2 wp = wr[j2];
                asm("fma.rn.f32x2 %0, %1, %2, %0;"
                    : "+l"(acc[2 * j2]) : "l"(xx), "l"(wp.x));
                asm("fma.rn.f32x2 %0, %1, %2, %0;"
                    : "+l"(acc[2 * j2 + 1]) : "l"(xx), "l"(wp.y));
            }
        }
#pragma unroll
        for (int j = 0; j < 16; j++) {
            float o0, o1;
            asm("mov.b64 {%0, %1}, %2;" : "=f"(o0), "=f"(o1) : "l"(acc[j]));
            o0 = leaky(o0, 0.2f);
            o1 = leaky(o1, 0.2f);
            int col0 = c0 + 2 * j;
            const float* w0 = sWr + col0 * 4;
            const float* w1 = sWr + (col0 + 1) * 4;
            f[0] += o0 * w0[0] + o1 * w1[0];
            f[1] += o0 * w0[1] + o1 * w1[1];
            f[2] += o0 * w0[2] + o1 * w1[2];
            f[3] += o0 * w0[3] + o1 * w1[3];
        }
    }
    reinterpret_cast<float4*>(out)[r] = make_float4(f[0], f[1], f[2], f[3]);
}

// ---------------------------------------------------------------------------
// CSR gather — TWO nodes per warp, interleaved (MLP 4 -> 8). Per-node FP
// order identical to the proven single-node loop (4-batches then tail).
__global__ void __launch_bounds__(256) gather_kernel() {
    int warp = (blockIdx.x * blockDim.x + threadIdx.x) >> 5;
    if (warp >= Nn / 2) return;
    int lane = threadIdx.x & 31;
    int nA = warp * 2;
    int nB = nA + 1;

    const __half2* nd = reinterpret_cast<const __half2*>(d_node);

    float2 sA = __half22float2(nd[(size_t)nA * 32 + lane]);
    float2 sB = __half22float2(nd[(size_t)nB * 32 + lane]);
    float snA = d_selfnorm[nA];
    float snB = d_selfnorm[nB];
    float ax = sA.x * snA, ay = sA.y * snA;
    float bx = sB.x * snB, by = sB.y * snB;

    int iA = d_off[nA];
    int eA = d_off[nA + 1];
    int iB = eA;  // CSR contiguity: off[nB] == off[nA+1]
    int eB = d_off[nB + 1];

    // interleaved: 4 edges of A + 4 edges of B per iteration (8 gathers in flight)
    while (iA + 4 <= eA && iB + 4 <= eB) {
        int sa0 = __ldg(&d_csr_src[iA + 0]);
        int sa1 = __ldg(&d_csr_src[iA + 1]);
        int sa2 = __ldg(&d_csr_src[iA + 2]);
        int sa3 = __ldg(&d_csr_src[iA + 3]);
        int sb0 = __ldg(&d_csr_src[iB + 0]);
        int sb1 = __ldg(&d_csr_src[iB + 1]);
        int sb2 = __ldg(&d_csr_src[iB + 2]);
        int sb3 = __ldg(&d_csr_src[iB + 3]);
        float wa0 = __ldg(&d_csr_w[iA + 0]);
        float wa1 = __ldg(&d_csr_w[iA + 1]);
        float wa2 = __ldg(&d_csr_w[iA + 2]);
        float wa3 = __ldg(&d_csr_w[iA + 3]);
        float wb0 = __ldg(&d_csr_w[iB + 0]);
        float wb1 = __ldg(&d_csr_w[iB + 1]);
        float wb2 = __ldg(&d_csr_w[iB + 2]);
        float wb3 = __ldg(&d_csr_w[iB + 3]);
        float2 va0 = __half22float2(nd[(size_t)sa0 * 32 + lane]);
        float2 va1 = __half22float2(nd[(size_t)sa1 * 32 + lane]);
        float2 va2 = __half22float2(nd[(size_t)sa2 * 32 + lane]);
        float2 va3 = __half22float2(nd[(size_t)sa3 * 32 + lane]);
        float2 vb0 = __half22float2(nd[(size_t)sb0 * 32 + lane]);
        float2 vb1 = __half22float2(nd[(size_t)sb1 * 32 + lane]);
        float2 vb2 = __half22float2(nd[(size_t)sb2 * 32 + lane]);
        float2 vb3 = __half22float2(nd[(size_t)sb3 * 32 + lane]);
        ax += va0.x * wa0; ay += va0.y * wa0;
        ax += va1.x * wa1; ay += va1.y * wa1;
        ax += va2.x * wa2; ay += va2.y * wa2;
        ax += va3.x * wa3; ay += va3.y * wa3;
        bx += vb0.x * wb0; by += vb0.y * wb0;
        bx += vb1.x * wb1; by += vb1.y * wb1;
        bx += vb2.x * wb2; by += vb2.y * wb2;
        bx += vb3.x * wb3; by += vb3.y * wb3;
        iA += 4; iB += 4;
    }
    // finish A
    for (; iA + 4 <= eA; iA += 4) {
        int s0 = __ldg(&d_csr_src[iA + 0]);
        int s1 = __ldg(&d_csr_src[iA + 1]);
        int s2 = __ldg(&d_csr_src[iA + 2]);
        int s3 = __ldg(&d_csr_src[iA + 3]);
        float w0 = __ldg(&d_csr_w[iA + 0]);
        float w1 = __ldg(&d_csr_w[iA + 1]);
        float w2 = __ldg(&d_csr_w[iA + 2]);
        float w3 = __ldg(&d_csr_w[iA + 3]);
        float2 v0 = __half22float2(nd[(size_t)s0 * 32 + lane]);
        float2 v1 = __half22float2(nd[(size_t)s1 * 32 + lane]);
        float2 v2 = __half22float2(nd[(size_t)s2 * 32 + lane]);
        float2 v3 = __half22float2(nd[(size_t)s3 * 32 + lane]);
        ax += v0.x * w0; ay += v0.y * w0;
        ax += v1.x * w1; ay += v1.y * w1;
        ax += v2.x * w2; ay += v2.y * w2;
        ax += v3.x * w3; ay += v3.y * w3;
    }
    for (; iA < eA; iA++) {
        int s = __ldg(&d_csr_src[iA]);
        float w = __ldg(&d_csr_w[iA]);
        float2 v = __half22float2(nd[(size_t)s * 32 + lane]);
        ax += v.x * w; ay += v.y * w;
    }
    // finish B
    for (; iB + 4 <= eB; iB += 4) {
        int s0 = __ldg(&d_csr_src[iB + 0]);
        int s1 = __ldg(&d_csr_src[iB + 1]);
        int s2 = __ldg(&d_csr_src[iB + 2]);
        int s3 = __ldg(&d_csr_src[iB + 3]);
        float w0 = __ldg(&d_csr_w[iB + 0]);
        float w1 = __ldg(&d_csr_w[iB + 1]);
        float w2 = __ldg(&d_csr_w[iB + 2]);
        float w3 = __ldg(&d_csr_w[iB + 3]);
        float2 v0 = __half22float2(nd[(size_t)s0 * 32 + lane]);
        float2 v1 = __half22float2(nd[(size_t)s1 * 32 + lane]);
        float2 v2 = __half22float2(nd[(size_t)s2 * 32 + lane]);
        float2 v3 = __half22float2(nd[(size_t)s3 * 32 + lane]);
        bx += v0.x * w0; by += v0.y * w0;
        bx += v1.x * w1; by += v1.y * w1;
        bx += v2.x * w2; by += v2.y * w2;
        bx += v3.x * w3; by += v3.y * w3;
    }
    for (; iB < eB; iB++) {
        int s = __ldg(&d_csr_src[iB]);
        float w = __ldg(&d_csr_w[iB]);
        float2 v = __half22float2(nd[(size_t)s * 32 + lane]);
        bx += v.x * w; by += v.y * w;
    }

    d_agg[(size_t)nA * 32 + lane] = pack2(ax, ay);
    d_agg[(size_t)nB * 32 + lane] = pack2(bx, by);
}

// ---------------------------------------------------------------------------
extern "C" void kernel_launch(void* const* d_in, const int* in_sizes, int n_in,
                              void* d_out, int out_size) {
    const float* x = (const float*)d_in[0];
    const int* ei = (const int*)d_in[1];
    const float* ea = (const float*)d_in[2];
    const float* Wn1 = (const float*)d_in[3];
    const float* bn1 = (const float*)d_in[4];
    const float* Wn2 = (const float*)d_in[5];
    const float* bn2 = (const float*)d_in[6];
    const float* We1 = (const float*)d_in[7];
    const float* be1 = (const float*)d_in[8];
    const float* We2 = (const float*)d_in[9];
    const float* be2 = (const float*)d_in[10];
    const float* Wg = (const float*)d_in[11];
    const float* bg = (const float*)d_in[12];
    const float* Wp1 = (const float*)d_in[13];
    const float* bp1 = (const float*)d_in[14];
    const float* Wp2 = (const float*)d_in[15];
    const float* bp2 = (const float*)d_in[16];
    const float* Wr = (const float*)d_in[17];
    const float* br = (const float*)d_in[18];

    const int NB = (Nn + 255) / 256;
    const int EB = (Ee + 255) / 256;
    const int GB = (Nn / 2 * 32 + 255) / 256;  // 2 nodes per warp
    const int TB = (Nn / 16 + 7) / 8;          // gemm_tc tiles

    // gcn_norm + CSR build + weight split
    init_kernel<<<NB, 256>>>();
    wsplit_kernel<<<128, 256>>>(Wg);
    edge_kernel<<<EB, 256>>>((const float4*)ea, ei, We1, be1, We2, be2);
    scan1_kernel<<<NTILES, SCAN_TILE>>>();
    scan2_kernel<<<1, 32>>>();
    scan3_kernel<<<NB, 256>>>();  // + dis/selfnorm fused
    fill_kernel<<<EB, 256>>>(ei);

    // fused node MLP: x -> d_node (fp16)
    node_mlp_kernel<<<NB, 256>>>(x, Wn1, bn1, Wn2, bn2);

    // 8 GCN layers: interleaved fp16 gather -> tensor-core GEMM (by layer idx)
    for (int i = 0; i < 8; i++) {
        gather_kernel<<<GB, 256>>>();
        gemm_tc_kernel<<<TB, 256>>>(i, bg + i * 64);
    }

    // fused post MLP + final projection
    post_mlp_kernel<<<NB, 256>>>(Wp1, bp1, Wp2, bp2, Wr, br, (float*)d_out);
}